// round 2
// baseline (speedup 1.0000x reference)
#include <cuda_runtime.h>
#include <math.h>
#include <float.h>

#define BATCH 8
#define NPTS  4096
#define CCH   256
#define DD    128
#define KNB   16

// Scratch (device globals; no allocation allowed)
__device__ float g_QK[BATCH * NPTS * (2 * DD)];   // [p][0:128]=Q, [128:256]=K  (33.5 MB)
__device__ float g_featT[BATCH * NPTS * CCH];      // features transposed to [b][n][c] (33.5 MB)
__device__ int   g_idx[BATCH * NPTS * KNB];        // knn indices (2 MB)

// ---------------------------------------------------------------------------
// Kernel 0: transpose fp4_features [B,C,N] -> [B,N,C] for contiguous gathers
// ---------------------------------------------------------------------------
__global__ void transpose_kernel(const float* __restrict__ feat) {
    __shared__ float tile[32][33];
    int b  = blockIdx.z;
    int c0 = blockIdx.x * 32;
    int n0 = blockIdx.y * 32;
    int tx = threadIdx.x, ty = threadIdx.y;
    const float* src = feat + (size_t)b * CCH * NPTS;
#pragma unroll
    for (int i = 0; i < 32; i += 8)
        tile[ty + i][tx] = src[(size_t)(c0 + ty + i) * NPTS + n0 + tx];
    __syncthreads();
    float* dst = g_featT + (size_t)b * NPTS * CCH;
#pragma unroll
    for (int i = 0; i < 32; i += 8)
        dst[(size_t)(n0 + ty + i) * CCH + c0 + tx] = tile[tx][ty + i];
}

// ---------------------------------------------------------------------------
// Kernel 1: KNN. One thread per query point, whole batch's xyz in smem.
// pd = 2*dot - |xi|^2 - |xj|^2  (matches reference; self gives exactly 0)
// Top-16 kept as an unsorted set; attention is permutation-invariant over it.
// ---------------------------------------------------------------------------
__global__ void knn_kernel(const float* __restrict__ xyz) {
    extern __shared__ float sm[];
    float* sx = sm;
    float* sy = sm + NPTS;
    float* sz = sm + 2 * NPTS;

    int b = blockIdx.x >> 4;
    int n = ((blockIdx.x & 15) << 8) + threadIdx.x;

    const float* base = xyz + (size_t)b * NPTS * 3;
    for (int i = threadIdx.x; i < NPTS; i += 256) {
        sx[i] = base[i * 3 + 0];
        sy[i] = base[i * 3 + 1];
        sz[i] = base[i * 3 + 2];
    }
    __syncthreads();

    float qx = sx[n], qy = sy[n], qz = sz[n];
    float xxi = fmaf(qx, qx, fmaf(qy, qy, qz * qz));

    float best[KNB];
    int   bidx[KNB];
#pragma unroll
    for (int t = 0; t < KNB; t++) { best[t] = -FLT_MAX; bidx[t] = 0; }
    float minv = -FLT_MAX;
    int   minpos = 0;

#pragma unroll 4
    for (int j = 0; j < NPTS; j++) {
        float xj = sx[j], yj = sy[j], zj = sz[j];
        float dot = fmaf(qx, xj, fmaf(qy, yj, qz * zj));
        float xxj = fmaf(xj, xj, fmaf(yj, yj, zj * zj));
        float pd  = fmaf(2.0f, dot, -xxi) - xxj;
        if (pd > minv) {
#pragma unroll
            for (int t = 0; t < KNB; t++)
                if (t == minpos) { best[t] = pd; bidx[t] = j; }
            minv = best[0]; minpos = 0;
#pragma unroll
            for (int t = 1; t < KNB; t++)
                if (best[t] < minv) { minv = best[t]; minpos = t; }
        }
    }

    int p = b * NPTS + n;
#pragma unroll
    for (int t = 0; t < KNB; t++) g_idx[p * KNB + t] = bidx[t];
}

// ---------------------------------------------------------------------------
// Kernel 2: fused Q/K SGEMM.  QK[p][e] = X[p]@W^T + bias, e<128 -> Wq, else Wk
// Block: 256 threads, 64 rows x 256 cols; per-thread 8x8 microtile (FP32).
// ---------------------------------------------------------------------------
#define PW 257
#define GEMM_SMEM ((128 * PW + 64 * 128 + 256) * 4)

__global__ void qk_gemm_kernel(const float* __restrict__ X,
                               const float* __restrict__ Wq, const float* __restrict__ bq,
                               const float* __restrict__ Wk, const float* __restrict__ bk) {
    extern __shared__ float sm[];
    float* sW = sm;                  // [128 k][257] transposed weights (cols 0:128 Wq, 128:256 Wk)
    float* sX = sm + 128 * PW;       // [64 rows][128]
    float* sB = sX + 64 * 128;       // [256] bias

    int tid = threadIdx.x;
    for (int i = tid; i < 128 * 128; i += 256) {
        int e = i >> 7, d = i & 127;
        sW[d * PW + e]       = Wq[i];   // Wq[e][d]
        sW[d * PW + 128 + e] = Wk[i];
    }
    if (tid < 128) { sB[tid] = bq[tid]; sB[128 + tid] = bk[tid]; }

    int row0 = blockIdx.x * 64;
    for (int i = tid; i < 64 * 128; i += 256)
        sX[i] = X[(size_t)row0 * 128 + i];
    __syncthreads();

    int w = tid >> 5, l = tid & 31;
    int rbase = w * 8;

    float acc[8][8];
#pragma unroll
    for (int r = 0; r < 8; r++)
#pragma unroll
        for (int m = 0; m < 8; m++) acc[r][m] = sB[l + 32 * m];

#pragma unroll 2
    for (int k = 0; k < 128; k++) {
        float xv[8], wv[8];
#pragma unroll
        for (int r = 0; r < 8; r++) xv[r] = sX[(rbase + r) * 128 + k];
#pragma unroll
        for (int m = 0; m < 8; m++) wv[m] = sW[k * PW + l + 32 * m];
#pragma unroll
        for (int r = 0; r < 8; r++)
#pragma unroll
            for (int m = 0; m < 8; m++)
                acc[r][m] = fmaf(xv[r], wv[m], acc[r][m]);
    }

#pragma unroll
    for (int r = 0; r < 8; r++) {
        size_t orow = (size_t)(row0 + rbase + r) * 256;
#pragma unroll
        for (int m = 0; m < 8; m++) g_QK[orow + l + 32 * m] = acc[r][m];
    }
}

// ---------------------------------------------------------------------------
// Kernel 3: fused scores + softmax + weighted feature gather + transposed write
// One warp per point (4 points/warp sequentially), 32 points per block.
// scores_j = Q[n] . K[idx_j] / sqrt(128)   (offset/bias terms cancel in softmax)
// ---------------------------------------------------------------------------
__global__ void attn_kernel(float* __restrict__ out) {
    __shared__ float s_out[CCH * 33];   // 33 KB: [c][point], pitch 33

    int tid = threadIdx.x;
    int w = tid >> 5, l = tid & 31;
    int p0 = blockIdx.x * 32;           // 32 points per block, all same batch
    int b  = p0 >> 12;
    int j    = l >> 1;                  // neighbor handled by this lane (dup x2)
    int half = l & 1;                   // which half of D

    for (int i = 0; i < 4; i++) {
        int p  = p0 + w * 4 + i;
        int nb = g_idx[p * KNB + j];

        const float4* qrow = (const float4*)(g_QK + (size_t)p * 256 + half * 64);
        const float4* krow = (const float4*)(g_QK + ((size_t)(b * NPTS) + nb) * 256 + 128 + half * 64);
        float part = 0.f;
#pragma unroll
        for (int m = 0; m < 16; m++) {
            float4 q4 = qrow[m], k4 = krow[m];
            part = fmaf(q4.x, k4.x, fmaf(q4.y, k4.y, fmaf(q4.z, k4.z, fmaf(q4.w, k4.w, part))));
        }
        part += __shfl_xor_sync(0xffffffffu, part, 1);
        float s = part * 0.08838834764831845f;   // 1/sqrt(128)

        float mx = s;
#pragma unroll
        for (int o = 16; o > 0; o >>= 1) mx = fmaxf(mx, __shfl_xor_sync(0xffffffffu, mx, o));
        float e = __expf(s - mx);
        float sum = e;
#pragma unroll
        for (int o = 16; o > 0; o >>= 1) sum += __shfl_xor_sync(0xffffffffu, sum, o);
        float a = e * (2.0f / sum);   // each j counted twice in sum

        // weighted gather: lane handles channels [8l, 8l+8)
        float4 acc0 = {0, 0, 0, 0}, acc1 = {0, 0, 0, 0};
#pragma unroll
        for (int jj = 0; jj < KNB; jj++) {
            float aj  = __shfl_sync(0xffffffffu, a,  jj * 2);
            int   nbj = __shfl_sync(0xffffffffu, nb, jj * 2);
            const float4* frow = (const float4*)(g_featT + ((size_t)(b * NPTS) + nbj) * 256 + l * 8);
            float4 f0 = frow[0], f1 = frow[1];
            acc0.x = fmaf(aj, f0.x, acc0.x); acc0.y = fmaf(aj, f0.y, acc0.y);
            acc0.z = fmaf(aj, f0.z, acc0.z); acc0.w = fmaf(aj, f0.w, acc0.w);
            acc1.x = fmaf(aj, f1.x, acc1.x); acc1.y = fmaf(aj, f1.y, acc1.y);
            acc1.z = fmaf(aj, f1.z, acc1.z); acc1.w = fmaf(aj, f1.w, acc1.w);
        }

        int pr = w * 4 + i;
        int c0 = l * 8;
        s_out[(c0 + 0) * 33 + pr] = acc0.x;
        s_out[(c0 + 1) * 33 + pr] = acc0.y;
        s_out[(c0 + 2) * 33 + pr] = acc0.z;
        s_out[(c0 + 3) * 33 + pr] = acc0.w;
        s_out[(c0 + 4) * 33 + pr] = acc1.x;
        s_out[(c0 + 5) * 33 + pr] = acc1.y;
        s_out[(c0 + 6) * 33 + pr] = acc1.z;
        s_out[(c0 + 7) * 33 + pr] = acc1.w;
    }
    __syncthreads();

    // coalesced transposed write: out[b][c][n]
    float* obase = out + (size_t)b * CCH * NPTS;
    int n0 = p0 & (NPTS - 1);
#pragma unroll
    for (int i = 0; i < 32; i++) {
        int linear = i * 256 + tid;
        int c  = linear >> 5;
        int nl = linear & 31;
        obase[(size_t)c * NPTS + n0 + nl] = s_out[c * 33 + nl];
    }
}

// ---------------------------------------------------------------------------
extern "C" void kernel_launch(void* const* d_in, const int* in_sizes, int n_in,
                              void* d_out, int out_size) {
    const float* xyz    = (const float*)d_in[0];
    const float* feat   = (const float*)d_in[1];
    const float* concat = (const float*)d_in[2];
    const float* Wq     = (const float*)d_in[3];
    const float* bq     = (const float*)d_in[4];
    const float* Wk     = (const float*)d_in[5];
    const float* bk     = (const float*)d_in[6];
    float* out = (float*)d_out;

    cudaFuncSetAttribute(knn_kernel, cudaFuncAttributeMaxDynamicSharedMemorySize, 3 * NPTS * 4);
    cudaFuncSetAttribute(qk_gemm_kernel, cudaFuncAttributeMaxDynamicSharedMemorySize, GEMM_SMEM);

    dim3 tgrid(CCH / 32, NPTS / 32, BATCH);
    transpose_kernel<<<tgrid, dim3(32, 8)>>>(feat);
    knn_kernel<<<BATCH * (NPTS / 256), 256, 3 * NPTS * 4>>>(xyz);
    qk_gemm_kernel<<<(BATCH * NPTS) / 64, 256, GEMM_SMEM>>>(concat, Wq, bq, Wk, bk);
    attn_kernel<<<(BATCH * NPTS) / 32, 256>>>(out);
}

// round 3
// speedup vs baseline: 1.2188x; 1.2188x over previous
#include <cuda_runtime.h>
#include <math.h>
#include <float.h>

#define BATCH 8
#define NPTS  4096
#define CCH   256
#define DD    128
#define KNB   16

// Scratch (device globals; no allocation allowed)
__device__ float g_QK[BATCH * NPTS * (2 * DD)];   // [p][0:128]=Q, [128:256]=K
__device__ float g_featT[BATCH * NPTS * CCH];      // features transposed to [b][n][c]
__device__ int   g_idx[BATCH * NPTS * KNB];        // knn indices

// ---------------------------------------------------------------------------
// Kernel 0: transpose fp4_features [B,C,N] -> [B,N,C] for contiguous gathers
// ---------------------------------------------------------------------------
__global__ void transpose_kernel(const float* __restrict__ feat) {
    __shared__ float tile[32][33];
    int b  = blockIdx.z;
    int c0 = blockIdx.x * 32;
    int n0 = blockIdx.y * 32;
    int tx = threadIdx.x, ty = threadIdx.y;
    const float* src = feat + (size_t)b * CCH * NPTS;
#pragma unroll
    for (int i = 0; i < 32; i += 8)
        tile[ty + i][tx] = src[(size_t)(c0 + ty + i) * NPTS + n0 + tx];
    __syncthreads();
    float* dst = g_featT + (size_t)b * NPTS * CCH;
#pragma unroll
    for (int i = 0; i < 32; i += 8)
        dst[(size_t)(n0 + ty + i) * CCH + c0 + tx] = tile[tx][ty + i];
}

// ---------------------------------------------------------------------------
// Kernel 1: KNN v2. TWO threads per query (each scans a stride-2 interleave),
// 512-thread blocks (256 queries), xyz cached in smem as float4 (x,y,z,|x|^2).
// Partial top-16 lists merged through smem. 16 warps/SM -> 4 warps/SMSP.
// ---------------------------------------------------------------------------
#define KNN_SMEM (NPTS * 16 + 256 * KNB * 8)

__device__ __forceinline__ void topk_insert(float pd, int j,
                                            float best[KNB], int bidx[KNB],
                                            float& minv, int& minpos) {
#pragma unroll
    for (int t = 0; t < KNB; t++)
        if (t == minpos) { best[t] = pd; bidx[t] = j; }
    minv = best[0]; minpos = 0;
#pragma unroll
    for (int t = 1; t < KNB; t++)
        if (best[t] < minv) { minv = best[t]; minpos = t; }
}

__global__ void knn_kernel(const float* __restrict__ xyz) {
    extern __shared__ float sm[];
    float4* sp   = (float4*)sm;                      // [4096] (x,y,z,xx)
    float*  mval = sm + NPTS * 4;                    // [256*16]
    int*    midx = (int*)(mval + 256 * KNB);         // [256*16]

    int tid = threadIdx.x;
    int b     = blockIdx.x >> 4;
    int qbase = (blockIdx.x & 15) << 8;

    const float* base = xyz + (size_t)b * NPTS * 3;
    for (int i = tid; i < NPTS; i += 512) {
        float x = base[i * 3 + 0], y = base[i * 3 + 1], z = base[i * 3 + 2];
        sp[i] = make_float4(x, y, z, fmaf(x, x, fmaf(y, y, z * z)));
    }
    __syncthreads();

    int qi = tid >> 1;          // local query 0..255
    int ph = tid & 1;           // which interleave this thread scans
    int n  = qbase + qi;

    float4 q = sp[n];
    float qx = q.x, qy = q.y, qz = q.z, xxi = q.w;

    float best[KNB];
    int   bidx[KNB];
#pragma unroll
    for (int t = 0; t < KNB; t++) { best[t] = -FLT_MAX; bidx[t] = 0; }
    float minv = -FLT_MAX;
    int   minpos = 0;

#pragma unroll 4
    for (int j = ph; j < NPTS; j += 2) {
        float4 c = sp[j];
        float dot = fmaf(qx, c.x, fmaf(qy, c.y, qz * c.z));
        float pd  = fmaf(2.0f, dot, -xxi) - c.w;
        if (pd > minv)
            topk_insert(pd, j, best, bidx, minv, minpos);
    }

    // merge: odd thread publishes its list, even thread folds it in
    if (ph == 1) {
#pragma unroll
        for (int t = 0; t < KNB; t++) {
            mval[qi * KNB + t] = best[t];
            midx[qi * KNB + t] = bidx[t];
        }
    }
    __syncthreads();
    if (ph == 0) {
#pragma unroll
        for (int t = 0; t < KNB; t++) {
            float pd = mval[qi * KNB + t];
            int   j  = midx[qi * KNB + t];
            if (pd > minv)
                topk_insert(pd, j, best, bidx, minv, minpos);
        }
        int p = b * NPTS + n;
#pragma unroll
        for (int t = 0; t < KNB; t++) g_idx[p * KNB + t] = bidx[t];
    }
}

// ---------------------------------------------------------------------------
// Kernel 2: fused Q/K SGEMM.  QK[p][e] = X[p]@W^T + bias, e<128 -> Wq, else Wk
// ---------------------------------------------------------------------------
#define PW 257
#define GEMM_SMEM ((128 * PW + 64 * 128 + 256) * 4)

__global__ void qk_gemm_kernel(const float* __restrict__ X,
                               const float* __restrict__ Wq, const float* __restrict__ bq,
                               const float* __restrict__ Wk, const float* __restrict__ bk) {
    extern __shared__ float sm[];
    float* sW = sm;                  // [128 k][257]
    float* sX = sm + 128 * PW;       // [64 rows][128]
    float* sB = sX + 64 * 128;       // [256] bias

    int tid = threadIdx.x;
    for (int i = tid; i < 128 * 128; i += 256) {
        int e = i >> 7, d = i & 127;
        sW[d * PW + e]       = Wq[i];
        sW[d * PW + 128 + e] = Wk[i];
    }
    if (tid < 128) { sB[tid] = bq[tid]; sB[128 + tid] = bk[tid]; }

    int row0 = blockIdx.x * 64;
    for (int i = tid; i < 64 * 128; i += 256)
        sX[i] = X[(size_t)row0 * 128 + i];
    __syncthreads();

    int w = tid >> 5, l = tid & 31;
    int rbase = w * 8;

    float acc[8][8];
#pragma unroll
    for (int r = 0; r < 8; r++)
#pragma unroll
        for (int m = 0; m < 8; m++) acc[r][m] = sB[l + 32 * m];

#pragma unroll 2
    for (int k = 0; k < 128; k++) {
        float xv[8], wv[8];
#pragma unroll
        for (int r = 0; r < 8; r++) xv[r] = sX[(rbase + r) * 128 + k];
#pragma unroll
        for (int m = 0; m < 8; m++) wv[m] = sW[k * PW + l + 32 * m];
#pragma unroll
        for (int r = 0; r < 8; r++)
#pragma unroll
            for (int m = 0; m < 8; m++)
                acc[r][m] = fmaf(xv[r], wv[m], acc[r][m]);
    }

#pragma unroll
    for (int r = 0; r < 8; r++) {
        size_t orow = (size_t)(row0 + rbase + r) * 256;
#pragma unroll
        for (int m = 0; m < 8; m++) g_QK[orow + l + 32 * m] = acc[r][m];
    }
}

// ---------------------------------------------------------------------------
// Kernel 3 v2: warp-cooperative scores + softmax + gather.
// One warp per point (4 points/warp). Lane l owns channel chunk [4l,4l+4)
// (and [128+4l,...) for the 256-ch gather) so every global load is a
// contiguous 512B warp access (4 L1 wavefronts) instead of a 1KB/16-row spread.
// ---------------------------------------------------------------------------
__global__ void __launch_bounds__(256) attn_kernel(float* __restrict__ out) {
    __shared__ float s_out[CCH * 33];

    int tid = threadIdx.x;
    int w = tid >> 5, l = tid & 31;
    int p0 = blockIdx.x * 32;
    int b  = p0 >> 12;

    for (int i = 0; i < 4; i++) {
        int p  = p0 + w * 4 + i;
        int nb = g_idx[p * KNB + (l & 15)];    // lanes 16-31 duplicate

        const float4* qv = (const float4*)(g_QK + (size_t)p * 256);
        float4 q4 = qv[l];                      // Q channels 4l..4l+3

        // partial dot products, one per neighbor, all lanes
        float pj[KNB];
#pragma unroll
        for (int jj = 0; jj < KNB; jj++) {
            int nbj = __shfl_sync(0xffffffffu, nb, jj);
            const float4* kv = (const float4*)(g_QK + ((size_t)(b * NPTS) + nbj) * 256 + 128);
            float4 k4 = kv[l];                  // contiguous 512B warp load
            pj[jj] = fmaf(q4.x, k4.x, fmaf(q4.y, k4.y, fmaf(q4.z, k4.z, q4.w * k4.w)));
        }
        // batched butterfly reduction: after this every lane has all 16 dots
#pragma unroll
        for (int off = 16; off; off >>= 1)
#pragma unroll
            for (int jj = 0; jj < KNB; jj++)
                pj[jj] += __shfl_xor_sync(0xffffffffu, pj[jj], off);

        // in-lane softmax (identical on every lane)
        float mx = pj[0];
#pragma unroll
        for (int jj = 1; jj < KNB; jj++) mx = fmaxf(mx, pj[jj]);
        float sum = 0.f;
#pragma unroll
        for (int jj = 0; jj < KNB; jj++) {
            pj[jj] = __expf((pj[jj] - mx) * 0.08838834764831845f);
            sum += pj[jj];
        }
        float inv = 1.0f / sum;

        // weighted gather: lane l accumulates channels 4l..4l+3 and 128+4l..
        float4 acc0 = {0, 0, 0, 0}, acc1 = {0, 0, 0, 0};
#pragma unroll
        for (int jj = 0; jj < KNB; jj++) {
            float a = pj[jj] * inv;
            int nbj = __shfl_sync(0xffffffffu, nb, jj);
            const float4* fv = (const float4*)(g_featT + ((size_t)(b * NPTS) + nbj) * 256);
            float4 f0 = fv[l];                  // ch 4l..4l+3
            float4 f1 = fv[32 + l];             // ch 128+4l..128+4l+3
            acc0.x = fmaf(a, f0.x, acc0.x); acc0.y = fmaf(a, f0.y, acc0.y);
            acc0.z = fmaf(a, f0.z, acc0.z); acc0.w = fmaf(a, f0.w, acc0.w);
            acc1.x = fmaf(a, f1.x, acc1.x); acc1.y = fmaf(a, f1.y, acc1.y);
            acc1.z = fmaf(a, f1.z, acc1.z); acc1.w = fmaf(a, f1.w, acc1.w);
        }

        int pr = w * 4 + i;
        int c0 = 4 * l;
        s_out[(c0 + 0) * 33 + pr] = acc0.x;
        s_out[(c0 + 1) * 33 + pr] = acc0.y;
        s_out[(c0 + 2) * 33 + pr] = acc0.z;
        s_out[(c0 + 3) * 33 + pr] = acc0.w;
        s_out[(128 + c0 + 0) * 33 + pr] = acc1.x;
        s_out[(128 + c0 + 1) * 33 + pr] = acc1.y;
        s_out[(128 + c0 + 2) * 33 + pr] = acc1.z;
        s_out[(128 + c0 + 3) * 33 + pr] = acc1.w;
    }
    __syncthreads();

    // coalesced transposed write: out[b][c][n]
    float* obase = out + (size_t)b * CCH * NPTS;
    int n0 = p0 & (NPTS - 1);
#pragma unroll
    for (int i = 0; i < 32; i++) {
        int linear = i * 256 + tid;
        int c  = linear >> 5;
        int nl = linear & 31;
        obase[(size_t)c * NPTS + n0 + nl] = s_out[c * 33 + nl];
    }
}

// ---------------------------------------------------------------------------
extern "C" void kernel_launch(void* const* d_in, const int* in_sizes, int n_in,
                              void* d_out, int out_size) {
    const float* xyz    = (const float*)d_in[0];
    const float* feat   = (const float*)d_in[1];
    const float* concat = (const float*)d_in[2];
    const float* Wq     = (const float*)d_in[3];
    const float* bq     = (const float*)d_in[4];
    const float* Wk     = (const float*)d_in[5];
    const float* bk     = (const float*)d_in[6];
    float* out = (float*)d_out;

    cudaFuncSetAttribute(knn_kernel, cudaFuncAttributeMaxDynamicSharedMemorySize, KNN_SMEM);
    cudaFuncSetAttribute(qk_gemm_kernel, cudaFuncAttributeMaxDynamicSharedMemorySize, GEMM_SMEM);

    dim3 tgrid(CCH / 32, NPTS / 32, BATCH);
    transpose_kernel<<<tgrid, dim3(32, 8)>>>(feat);
    knn_kernel<<<BATCH * (NPTS / 256), 512, KNN_SMEM>>>(xyz);
    qk_gemm_kernel<<<(BATCH * NPTS) / 64, 256, GEMM_SMEM>>>(concat, Wq, bq, Wk, bk);
    attn_kernel<<<(BATCH * NPTS) / 32, 256>>>(out);
}

// round 4
// speedup vs baseline: 1.8506x; 1.5183x over previous
#include <cuda_runtime.h>
#include <math.h>
#include <float.h>

#define BATCH 8
#define NPTS  4096
#define CCH   256
#define DD    128
#define KNB   16

// Scratch (device globals; no allocation allowed)
__device__ float g_QK[BATCH * NPTS * (2 * DD)];   // [p][0:128]=Q, [128:256]=K
__device__ float g_featT[BATCH * NPTS * CCH];      // features transposed to [b][n][c]
__device__ int   g_idx[BATCH * NPTS * KNB];        // knn indices

// ---------------------------------------------------------------------------
// Kernel 0: transpose fp4_features [B,C,N] -> [B,N,C] for contiguous gathers
// ---------------------------------------------------------------------------
__global__ void transpose_kernel(const float* __restrict__ feat) {
    __shared__ float tile[32][33];
    int b  = blockIdx.z;
    int c0 = blockIdx.x * 32;
    int n0 = blockIdx.y * 32;
    int tx = threadIdx.x, ty = threadIdx.y;
    const float* src = feat + (size_t)b * CCH * NPTS;
#pragma unroll
    for (int i = 0; i < 32; i += 8)
        tile[ty + i][tx] = src[(size_t)(c0 + ty + i) * NPTS + n0 + tx];
    __syncthreads();
    float* dst = g_featT + (size_t)b * NPTS * CCH;
#pragma unroll
    for (int i = 0; i < 32; i += 8)
        dst[(size_t)(n0 + ty + i) * CCH + c0 + tx] = tile[tx][ty + i];
}

// ---------------------------------------------------------------------------
// Kernel 1: KNN v3 — warp-cooperative. One warp per query (4 queries/warp
// sequentially). 32 candidates per iteration, one ballot vs the running
// 16th-best threshold; top-16 kept as a SORTED list across lanes 0..15
// (descending, lane 15 = threshold). Inserts are rare events (~120/query)
// and cost ~14 instr each via shuffle-shift. No per-iteration divergence.
// ---------------------------------------------------------------------------
#define KNN_BLOCK 256
#define KNN_SMEM  (NPTS * 16)

__global__ void __launch_bounds__(KNN_BLOCK) knn_kernel(const float* __restrict__ xyz) {
    extern __shared__ float4 sp[];            // [4096] (x,y,z,|x|^2)  64KB

    int tid = threadIdx.x;
    int b     = blockIdx.x >> 7;              // 128 blocks per batch
    int qbase = (blockIdx.x & 127) * 32;      // 32 queries per block

    const float* base = xyz + (size_t)b * NPTS * 3;
    for (int i = tid; i < NPTS; i += KNN_BLOCK) {
        float x = base[i * 3 + 0], y = base[i * 3 + 1], z = base[i * 3 + 2];
        sp[i] = make_float4(x, y, z, fmaf(x, x, fmaf(y, y, z * z)));
    }
    __syncthreads();

    int w = tid >> 5, l = tid & 31;

    for (int qq = 0; qq < 4; qq++) {
        int n = qbase + w * 4 + qq;
        float4 q = sp[n];
        float qx = q.x, qy = q.y, qz = q.z, xxi = q.w;

        float val = -FLT_MAX;                 // sorted list entry (lanes 0..15)
        int   idx = 0;
        float thr = -FLT_MAX;                 // list[15]

        for (int c0 = 0; c0 < NPTS; c0 += 32) {
            float4 c = sp[c0 + l];
            float dot = fmaf(qx, c.x, fmaf(qy, c.y, qz * c.z));
            float pd  = fmaf(2.0f, dot, -xxi) - c.w;

            unsigned mask = __ballot_sync(0xffffffffu, pd > thr);
            while (mask) {                    // uniform loop (mask from ballot)
                int s = __ffs(mask) - 1;
                mask &= mask - 1;
                float v = __shfl_sync(0xffffffffu, pd, s);
                if (v > thr) {                // re-check vs updated threshold (uniform)
                    int j = c0 + s;
                    float upv = __shfl_up_sync(0xffffffffu, val, 1);
                    int   upi = __shfl_up_sync(0xffffffffu, idx, 1);
                    bool pr = (l < 16) && (val < v);
                    unsigned pm = __ballot_sync(0xffffffffu, pr);
                    int pos = __ffs(pm) - 1;
                    if (pr) {
                        val = (l == pos) ? v : upv;
                        idx = (l == pos) ? j : upi;
                    }
                    thr = __shfl_sync(0xffffffffu, val, 15);
                }
            }
        }

        if (l < 16) g_idx[(size_t)(b * NPTS + n) * KNB + l] = idx;
    }
}

// ---------------------------------------------------------------------------
// Kernel 2: fused Q/K SGEMM.  QK[p][e] = X[p]@W^T + bias, e<128 -> Wq, else Wk
// ---------------------------------------------------------------------------
#define PW 257
#define GEMM_SMEM ((128 * PW + 64 * 128 + 256) * 4)

__global__ void qk_gemm_kernel(const float* __restrict__ X,
                               const float* __restrict__ Wq, const float* __restrict__ bq,
                               const float* __restrict__ Wk, const float* __restrict__ bk) {
    extern __shared__ float sm[];
    float* sW = sm;                  // [128 k][257]
    float* sX = sm + 128 * PW;       // [64 rows][128]
    float* sB = sX + 64 * 128;       // [256] bias

    int tid = threadIdx.x;
    for (int i = tid; i < 128 * 128; i += 256) {
        int e = i >> 7, d = i & 127;
        sW[d * PW + e]       = Wq[i];
        sW[d * PW + 128 + e] = Wk[i];
    }
    if (tid < 128) { sB[tid] = bq[tid]; sB[128 + tid] = bk[tid]; }

    int row0 = blockIdx.x * 64;
    for (int i = tid; i < 64 * 128; i += 256)
        sX[i] = X[(size_t)row0 * 128 + i];
    __syncthreads();

    int w = tid >> 5, l = tid & 31;
    int rbase = w * 8;

    float acc[8][8];
#pragma unroll
    for (int r = 0; r < 8; r++)
#pragma unroll
        for (int m = 0; m < 8; m++) acc[r][m] = sB[l + 32 * m];

#pragma unroll 2
    for (int k = 0; k < 128; k++) {
        float xv[8], wv[8];
#pragma unroll
        for (int r = 0; r < 8; r++) xv[r] = sX[(rbase + r) * 128 + k];
#pragma unroll
        for (int m = 0; m < 8; m++) wv[m] = sW[k * PW + l + 32 * m];
#pragma unroll
        for (int r = 0; r < 8; r++)
#pragma unroll
            for (int m = 0; m < 8; m++)
                acc[r][m] = fmaf(xv[r], wv[m], acc[r][m]);
    }

#pragma unroll
    for (int r = 0; r < 8; r++) {
        size_t orow = (size_t)(row0 + rbase + r) * 256;
#pragma unroll
        for (int m = 0; m < 8; m++) g_QK[orow + l + 32 * m] = acc[r][m];
    }
}

// ---------------------------------------------------------------------------
// Kernel 3: warp-cooperative scores + softmax + gather (unchanged from R3).
// ---------------------------------------------------------------------------
__global__ void __launch_bounds__(256) attn_kernel(float* __restrict__ out) {
    __shared__ float s_out[CCH * 33];

    int tid = threadIdx.x;
    int w = tid >> 5, l = tid & 31;
    int p0 = blockIdx.x * 32;
    int b  = p0 >> 12;

    for (int i = 0; i < 4; i++) {
        int p  = p0 + w * 4 + i;
        int nb = g_idx[p * KNB + (l & 15)];    // lanes 16-31 duplicate

        const float4* qv = (const float4*)(g_QK + (size_t)p * 256);
        float4 q4 = qv[l];                      // Q channels 4l..4l+3

        float pj[KNB];
#pragma unroll
        for (int jj = 0; jj < KNB; jj++) {
            int nbj = __shfl_sync(0xffffffffu, nb, jj);
            const float4* kv = (const float4*)(g_QK + ((size_t)(b * NPTS) + nbj) * 256 + 128);
            float4 k4 = kv[l];
            pj[jj] = fmaf(q4.x, k4.x, fmaf(q4.y, k4.y, fmaf(q4.z, k4.z, q4.w * k4.w)));
        }
#pragma unroll
        for (int off = 16; off; off >>= 1)
#pragma unroll
            for (int jj = 0; jj < KNB; jj++)
                pj[jj] += __shfl_xor_sync(0xffffffffu, pj[jj], off);

        float mx = pj[0];
#pragma unroll
        for (int jj = 1; jj < KNB; jj++) mx = fmaxf(mx, pj[jj]);
        float sum = 0.f;
#pragma unroll
        for (int jj = 0; jj < KNB; jj++) {
            pj[jj] = __expf((pj[jj] - mx) * 0.08838834764831845f);
            sum += pj[jj];
        }
        float inv = 1.0f / sum;

        float4 acc0 = {0, 0, 0, 0}, acc1 = {0, 0, 0, 0};
#pragma unroll
        for (int jj = 0; jj < KNB; jj++) {
            float a = pj[jj] * inv;
            int nbj = __shfl_sync(0xffffffffu, nb, jj);
            const float4* fv = (const float4*)(g_featT + ((size_t)(b * NPTS) + nbj) * 256);
            float4 f0 = fv[l];
            float4 f1 = fv[32 + l];
            acc0.x = fmaf(a, f0.x, acc0.x); acc0.y = fmaf(a, f0.y, acc0.y);
            acc0.z = fmaf(a, f0.z, acc0.z); acc0.w = fmaf(a, f0.w, acc0.w);
            acc1.x = fmaf(a, f1.x, acc1.x); acc1.y = fmaf(a, f1.y, acc1.y);
            acc1.z = fmaf(a, f1.z, acc1.z); acc1.w = fmaf(a, f1.w, acc1.w);
        }

        int pr = w * 4 + i;
        int c0 = 4 * l;
        s_out[(c0 + 0) * 33 + pr] = acc0.x;
        s_out[(c0 + 1) * 33 + pr] = acc0.y;
        s_out[(c0 + 2) * 33 + pr] = acc0.z;
        s_out[(c0 + 3) * 33 + pr] = acc0.w;
        s_out[(128 + c0 + 0) * 33 + pr] = acc1.x;
        s_out[(128 + c0 + 1) * 33 + pr] = acc1.y;
        s_out[(128 + c0 + 2) * 33 + pr] = acc1.z;
        s_out[(128 + c0 + 3) * 33 + pr] = acc1.w;
    }
    __syncthreads();

    float* obase = out + (size_t)b * CCH * NPTS;
    int n0 = p0 & (NPTS - 1);
#pragma unroll
    for (int i = 0; i < 32; i++) {
        int linear = i * 256 + tid;
        int c  = linear >> 5;
        int nl = linear & 31;
        obase[(size_t)c * NPTS + n0 + nl] = s_out[c * 33 + nl];
    }
}

// ---------------------------------------------------------------------------
extern "C" void kernel_launch(void* const* d_in, const int* in_sizes, int n_in,
                              void* d_out, int out_size) {
    const float* xyz    = (const float*)d_in[0];
    const float* feat   = (const float*)d_in[1];
    const float* concat = (const float*)d_in[2];
    const float* Wq     = (const float*)d_in[3];
    const float* bq     = (const float*)d_in[4];
    const float* Wk     = (const float*)d_in[5];
    const float* bk     = (const float*)d_in[6];
    float* out = (float*)d_out;

    cudaFuncSetAttribute(knn_kernel, cudaFuncAttributeMaxDynamicSharedMemorySize, KNN_SMEM);
    cudaFuncSetAttribute(qk_gemm_kernel, cudaFuncAttributeMaxDynamicSharedMemorySize, GEMM_SMEM);

    dim3 tgrid(CCH / 32, NPTS / 32, BATCH);
    transpose_kernel<<<tgrid, dim3(32, 8)>>>(feat);
    knn_kernel<<<BATCH * 128, KNN_BLOCK, KNN_SMEM>>>(xyz);
    qk_gemm_kernel<<<(BATCH * NPTS) / 64, 256, GEMM_SMEM>>>(concat, Wq, bq, Wk, bk);
    attn_kernel<<<(BATCH * NPTS) / 32, 256>>>(out);
}

// round 5
// speedup vs baseline: 2.0345x; 1.0994x over previous
#include <cuda_runtime.h>
#include <math.h>
#include <float.h>

#define BATCH 8
#define NPTS  4096
#define CCH   256
#define DD    128
#define KNB   16

__device__ float g_QK[BATCH * NPTS * (2 * DD)];   // [p][0:128]=Q, [128:256]=K
__device__ float g_featT[BATCH * NPTS * CCH];      // [b][n][c]
__device__ int   g_idx[BATCH * NPTS * KNB];

// ---------------------------------------------------------------------------
// Kernel 0: transpose fp4_features [B,C,N] -> [B,N,C]
// ---------------------------------------------------------------------------
__global__ void transpose_kernel(const float* __restrict__ feat) {
    __shared__ float tile[32][33];
    int b  = blockIdx.z;
    int c0 = blockIdx.x * 32;
    int n0 = blockIdx.y * 32;
    int tx = threadIdx.x, ty = threadIdx.y;
    const float* src = feat + (size_t)b * CCH * NPTS;
#pragma unroll
    for (int i = 0; i < 32; i += 8)
        tile[ty + i][tx] = src[(size_t)(c0 + ty + i) * NPTS + n0 + tx];
    __syncthreads();
    float* dst = g_featT + (size_t)b * NPTS * CCH;
#pragma unroll
    for (int i = 0; i < 32; i += 8)
        dst[(size_t)(n0 + ty + i) * CCH + c0 + tx] = tile[tx][ty + i];
}

// ---------------------------------------------------------------------------
// Kernel 1: KNN v4 — warp-cooperative, bitonic init + lazy threshold.
// Sorted top-16 (descending) lives in lanes 0..15. First 32 candidates are
// seeded via a full-warp bitonic sort. Events: ballot vs a lazily-refreshed
// threshold; exact insert decided by ballot(val < v) (pm==0 => no-op), so a
// stale thr never corrupts the list.
// ---------------------------------------------------------------------------
#define KNN_BLOCK 256
#define KNN_SMEM  (NPTS * 16)

__global__ void __launch_bounds__(KNN_BLOCK) knn_kernel(const float* __restrict__ xyz) {
    extern __shared__ float4 sp[];            // [4096] (x,y,z,|x|^2)  64KB

    int tid = threadIdx.x;
    int b     = blockIdx.x >> 7;
    int qbase = (blockIdx.x & 127) * 32;

    const float* base = xyz + (size_t)b * NPTS * 3;
    for (int i = tid; i < NPTS; i += KNN_BLOCK) {
        float x = base[i * 3 + 0], y = base[i * 3 + 1], z = base[i * 3 + 2];
        sp[i] = make_float4(x, y, z, fmaf(x, x, fmaf(y, y, z * z)));
    }
    __syncthreads();

    int w = tid >> 5, l = tid & 31;

    for (int qq = 0; qq < 4; qq++) {
        int n = qbase + w * 4 + qq;
        float4 q = sp[n];
        float qx = q.x, qy = q.y, qz = q.z, xxi = q.w;

        // --- seed: first 32 candidates, full-warp bitonic sort (descending) ---
        float4 c0v = sp[l];
        float val = fmaf(2.0f, fmaf(qx, c0v.x, fmaf(qy, c0v.y, qz * c0v.z)), -xxi) - c0v.w;
        int   idx = l;
#pragma unroll
        for (int ksz = 2; ksz <= 32; ksz <<= 1) {
#pragma unroll
            for (int jsz = ksz >> 1; jsz > 0; jsz >>= 1) {
                float ov = __shfl_xor_sync(0xffffffffu, val, jsz);
                int   oi = __shfl_xor_sync(0xffffffffu, idx, jsz);
                bool keepBig = ((l & jsz) == 0) == ((l & ksz) == 0);
                bool take = keepBig ? (ov > val) : (ov < val);
                if (take) { val = ov; idx = oi; }
            }
        }
        float thr = __shfl_sync(0xffffffffu, val, 15);

        // --- main scan ---
        for (int c0 = 32; c0 < NPTS; c0 += 32) {
            float4 c = sp[c0 + l];
            float dot = fmaf(qx, c.x, fmaf(qy, c.y, qz * c.z));
            float pd  = fmaf(2.0f, dot, -xxi) - c.w;

            unsigned mask = __ballot_sync(0xffffffffu, pd > thr);
            if (mask) {
                do {
                    int s = __ffs(mask) - 1;
                    mask &= mask - 1;
                    float v = __shfl_sync(0xffffffffu, pd, s);
                    float upv = __shfl_up_sync(0xffffffffu, val, 1);
                    int   upi = __shfl_up_sync(0xffffffffu, idx, 1);
                    bool pr = (l < 16) && (val < v);
                    unsigned pm = __ballot_sync(0xffffffffu, pr);
                    if (pm) {
                        int pos = __ffs(pm) - 1;
                        if (pr) {
                            int j = c0 + s;
                            val = (l == pos) ? v : upv;
                            idx = (l == pos) ? j : upi;
                        }
                    }
                } while (mask);
                thr = __shfl_sync(0xffffffffu, val, 15);   // refresh once/iteration
            }
        }

        if (l < 16) g_idx[(size_t)(b * NPTS + n) * KNB + l] = idx;
    }
}

// ---------------------------------------------------------------------------
// Kernel 2: Q/K SGEMM v2. Each block: 64 rows x 128 cols, g=0 -> Wq, g=1 -> Wk.
// smem 98.8KB -> 2 blocks/SM. k unrolled x4 with float4 X loads.
// ---------------------------------------------------------------------------
#define WPITCH 129
#define GEMM_SMEM ((128 * WPITCH + 64 * 128) * 4)

__global__ void __launch_bounds__(256) qk_gemm_kernel(
        const float* __restrict__ X,
        const float* __restrict__ Wq, const float* __restrict__ bq,
        const float* __restrict__ Wk, const float* __restrict__ bk) {
    extern __shared__ float sm[];
    float* sWT = sm;                   // [k=128][pitch 129], W^T (conflict-free both ways)
    float* sX  = sm + 128 * WPITCH;    // [64][128]

    int tid  = threadIdx.x;
    int g    = blockIdx.x & 1;
    int row0 = (blockIdx.x >> 1) * 64;
    const float* W    = g ? Wk : Wq;
    const float* bias = g ? bk : bq;

    for (int i = tid; i < 128 * 128; i += 256) {
        int e = i >> 7, d = i & 127;
        sWT[d * WPITCH + e] = W[i];
    }
    for (int i = tid; i < 64 * 128; i += 256)
        sX[i] = X[(size_t)row0 * 128 + i];
    __syncthreads();

    int w = tid >> 5, l = tid & 31;
    int rbase = w * 8;

    float acc[8][4];
    float bm[4];
#pragma unroll
    for (int m = 0; m < 4; m++) bm[m] = __ldg(&bias[l + 32 * m]);
#pragma unroll
    for (int r = 0; r < 8; r++)
#pragma unroll
        for (int m = 0; m < 4; m++) acc[r][m] = bm[m];

    const float4* sX4 = (const float4*)sX;   // row pitch = 32 float4
#pragma unroll 2
    for (int k4 = 0; k4 < 32; k4++) {
        float4 xv[8];
#pragma unroll
        for (int r = 0; r < 8; r++) xv[r] = sX4[(rbase + r) * 32 + k4];
        float wv0[4], wv1[4], wv2[4], wv3[4];
#pragma unroll
        for (int m = 0; m < 4; m++) {
            int bidx = (4 * k4) * WPITCH + l + 32 * m;
            wv0[m] = sWT[bidx];
            wv1[m] = sWT[bidx + WPITCH];
            wv2[m] = sWT[bidx + 2 * WPITCH];
            wv3[m] = sWT[bidx + 3 * WPITCH];
        }
#pragma unroll
        for (int r = 0; r < 8; r++)
#pragma unroll
            for (int m = 0; m < 4; m++) {
                float a = acc[r][m];
                a = fmaf(xv[r].x, wv0[m], a);
                a = fmaf(xv[r].y, wv1[m], a);
                a = fmaf(xv[r].z, wv2[m], a);
                a = fmaf(xv[r].w, wv3[m], a);
                acc[r][m] = a;
            }
    }

#pragma unroll
    for (int r = 0; r < 8; r++) {
        size_t orow = (size_t)(row0 + rbase + r) * 256 + g * 128;
#pragma unroll
        for (int m = 0; m < 4; m++) g_QK[orow + l + 32 * m] = acc[r][m];
    }
}

// ---------------------------------------------------------------------------
// Kernel 3: warp-cooperative scores + softmax + gather (unchanged).
// ---------------------------------------------------------------------------
__global__ void __launch_bounds__(256) attn_kernel(float* __restrict__ out) {
    __shared__ float s_out[CCH * 33];

    int tid = threadIdx.x;
    int w = tid >> 5, l = tid & 31;
    int p0 = blockIdx.x * 32;
    int b  = p0 >> 12;

    for (int i = 0; i < 4; i++) {
        int p  = p0 + w * 4 + i;
        int nb = g_idx[p * KNB + (l & 15)];

        const float4* qv = (const float4*)(g_QK + (size_t)p * 256);
        float4 q4 = qv[l];

        float pj[KNB];
#pragma unroll
        for (int jj = 0; jj < KNB; jj++) {
            int nbj = __shfl_sync(0xffffffffu, nb, jj);
            const float4* kv = (const float4*)(g_QK + ((size_t)(b * NPTS) + nbj) * 256 + 128);
            float4 k4 = kv[l];
            pj[jj] = fmaf(q4.x, k4.x, fmaf(q4.y, k4.y, fmaf(q4.z, k4.z, q4.w * k4.w)));
        }
#pragma unroll
        for (int off = 16; off; off >>= 1)
#pragma unroll
            for (int jj = 0; jj < KNB; jj++)
                pj[jj] += __shfl_xor_sync(0xffffffffu, pj[jj], off);

        float mx = pj[0];
#pragma unroll
        for (int jj = 1; jj < KNB; jj++) mx = fmaxf(mx, pj[jj]);
        float sum = 0.f;
#pragma unroll
        for (int jj = 0; jj < KNB; jj++) {
            pj[jj] = __expf((pj[jj] - mx) * 0.08838834764831845f);
            sum += pj[jj];
        }
        float inv = 1.0f / sum;

        float4 acc0 = {0, 0, 0, 0}, acc1 = {0, 0, 0, 0};
#pragma unroll
        for (int jj = 0; jj < KNB; jj++) {
            float a = pj[jj] * inv;
            int nbj = __shfl_sync(0xffffffffu, nb, jj);
            const float4* fv = (const float4*)(g_featT + ((size_t)(b * NPTS) + nbj) * 256);
            float4 f0 = fv[l];
            float4 f1 = fv[32 + l];
            acc0.x = fmaf(a, f0.x, acc0.x); acc0.y = fmaf(a, f0.y, acc0.y);
            acc0.z = fmaf(a, f0.z, acc0.z); acc0.w = fmaf(a, f0.w, acc0.w);
            acc1.x = fmaf(a, f1.x, acc1.x); acc1.y = fmaf(a, f1.y, acc1.y);
            acc1.z = fmaf(a, f1.z, acc1.z); acc1.w = fmaf(a, f1.w, acc1.w);
        }

        int pr = w * 4 + i;
        int c0 = 4 * l;
        s_out[(c0 + 0) * 33 + pr] = acc0.x;
        s_out[(c0 + 1) * 33 + pr] = acc0.y;
        s_out[(c0 + 2) * 33 + pr] = acc0.z;
        s_out[(c0 + 3) * 33 + pr] = acc0.w;
        s_out[(128 + c0 + 0) * 33 + pr] = acc1.x;
        s_out[(128 + c0 + 1) * 33 + pr] = acc1.y;
        s_out[(128 + c0 + 2) * 33 + pr] = acc1.z;
        s_out[(128 + c0 + 3) * 33 + pr] = acc1.w;
    }
    __syncthreads();

    float* obase = out + (size_t)b * CCH * NPTS;
    int n0 = p0 & (NPTS - 1);
#pragma unroll
    for (int i = 0; i < 32; i++) {
        int linear = i * 256 + tid;
        int c  = linear >> 5;
        int nl = linear & 31;
        obase[(size_t)c * NPTS + n0 + nl] = s_out[c * 33 + nl];
    }
}

// ---------------------------------------------------------------------------
extern "C" void kernel_launch(void* const* d_in, const int* in_sizes, int n_in,
                              void* d_out, int out_size) {
    const float* xyz    = (const float*)d_in[0];
    const float* feat   = (const float*)d_in[1];
    const float* concat = (const float*)d_in[2];
    const float* Wq     = (const float*)d_in[3];
    const float* bq     = (const float*)d_in[4];
    const float* Wk     = (const float*)d_in[5];
    const float* bk     = (const float*)d_in[6];
    float* out = (float*)d_out;

    cudaFuncSetAttribute(knn_kernel, cudaFuncAttributeMaxDynamicSharedMemorySize, KNN_SMEM);
    cudaFuncSetAttribute(qk_gemm_kernel, cudaFuncAttributeMaxDynamicSharedMemorySize, GEMM_SMEM);

    dim3 tgrid(CCH / 32, NPTS / 32, BATCH);
    transpose_kernel<<<tgrid, dim3(32, 8)>>>(feat);
    knn_kernel<<<BATCH * 128, KNN_BLOCK, KNN_SMEM>>>(xyz);
    qk_gemm_kernel<<<(BATCH * NPTS / 64) * 2, 256, GEMM_SMEM>>>(concat, Wq, bq, Wk, bk);
    attn_kernel<<<(BATCH * NPTS) / 32, 256>>>(out);
}

// round 7
// speedup vs baseline: 2.5079x; 1.2327x over previous
#include <cuda_runtime.h>
#include <cuda_fp16.h>
#include <math.h>
#include <float.h>

#define BATCH 8
#define NPTS  4096
#define CCH   256
#define DD    128
#define KNB   16

__device__ float  g_QK[BATCH * NPTS * (2 * DD)];   // [p][0:128]=Q, [128:256]=K
__device__ __half g_featT[BATCH * NPTS * CCH];      // [b][n][c] fp16
__device__ int    g_idx[BATCH * NPTS * KNB];

// ---------------------------------------------------------------------------
// Kernel 0: transpose fp4_features [B,C,N] -> [B,N,C], fp32 -> fp16
// ---------------------------------------------------------------------------
__global__ void transpose_kernel(const float* __restrict__ feat) {
    __shared__ float tile[32][33];
    int b  = blockIdx.z;
    int c0 = blockIdx.x * 32;
    int n0 = blockIdx.y * 32;
    int tx = threadIdx.x, ty = threadIdx.y;
    const float* src = feat + (size_t)b * CCH * NPTS;
#pragma unroll
    for (int i = 0; i < 32; i += 8)
        tile[ty + i][tx] = src[(size_t)(c0 + ty + i) * NPTS + n0 + tx];
    __syncthreads();
    __half* dst = g_featT + (size_t)b * NPTS * CCH;
#pragma unroll
    for (int i = 0; i < 32; i += 8)
        dst[(size_t)(n0 + ty + i) * CCH + c0 + tx] = __float2half_rn(tile[tx][ty + i]);
}

// ---------------------------------------------------------------------------
// Kernel 1: KNN — warp-cooperative, bitonic init + lazy threshold.
// v5: 512-thread blocks (64 queries/block) -> 48 warps/SM for latency hiding.
// ---------------------------------------------------------------------------
#define KNN_BLOCK 512
#define KNN_SMEM  (NPTS * 16)

__global__ void __launch_bounds__(KNN_BLOCK) knn_kernel(const float* __restrict__ xyz) {
    extern __shared__ float4 sp[];            // [4096] (x,y,z,|x|^2)  64KB

    int tid = threadIdx.x;
    int b     = blockIdx.x >> 6;              // 64 blocks per batch
    int qbase = (blockIdx.x & 63) * 64;       // 64 queries per block

    const float* base = xyz + (size_t)b * NPTS * 3;
    for (int i = tid; i < NPTS; i += KNN_BLOCK) {
        float x = base[i * 3 + 0], y = base[i * 3 + 1], z = base[i * 3 + 2];
        sp[i] = make_float4(x, y, z, fmaf(x, x, fmaf(y, y, z * z)));
    }
    __syncthreads();

    int w = tid >> 5, l = tid & 31;

    for (int qq = 0; qq < 4; qq++) {
        int n = qbase + w * 4 + qq;
        float4 q = sp[n];
        float qx = q.x, qy = q.y, qz = q.z, xxi = q.w;

        // seed: first 32 candidates via full-warp bitonic sort (descending)
        float4 c0v = sp[l];
        float val = fmaf(2.0f, fmaf(qx, c0v.x, fmaf(qy, c0v.y, qz * c0v.z)), -xxi) - c0v.w;
        int   idx = l;
#pragma unroll
        for (int ksz = 2; ksz <= 32; ksz <<= 1) {
#pragma unroll
            for (int jsz = ksz >> 1; jsz > 0; jsz >>= 1) {
                float ov = __shfl_xor_sync(0xffffffffu, val, jsz);
                int   oi = __shfl_xor_sync(0xffffffffu, idx, jsz);
                bool keepBig = ((l & jsz) == 0) == ((l & ksz) == 0);
                bool take = keepBig ? (ov > val) : (ov < val);
                if (take) { val = ov; idx = oi; }
            }
        }
        float thr = __shfl_sync(0xffffffffu, val, 15);

        // main scan
        for (int c0 = 32; c0 < NPTS; c0 += 32) {
            float4 c = sp[c0 + l];
            float dot = fmaf(qx, c.x, fmaf(qy, c.y, qz * c.z));
            float pd  = fmaf(2.0f, dot, -xxi) - c.w;

            unsigned mask = __ballot_sync(0xffffffffu, pd > thr);
            if (mask) {
                do {
                    int s = __ffs(mask) - 1;
                    mask &= mask - 1;
                    float v = __shfl_sync(0xffffffffu, pd, s);
                    float upv = __shfl_up_sync(0xffffffffu, val, 1);
                    int   upi = __shfl_up_sync(0xffffffffu, idx, 1);
                    bool pr = (l < 16) && (val < v);
                    unsigned pm = __ballot_sync(0xffffffffu, pr);
                    if (pm) {
                        int pos = __ffs(pm) - 1;
                        if (pr) {
                            int j = c0 + s;
                            val = (l == pos) ? v : upv;
                            idx = (l == pos) ? j : upi;
                        }
                    }
                } while (mask);
                thr = __shfl_sync(0xffffffffu, val, 15);
            }
        }

        if (l < 16) g_idx[(size_t)(b * NPTS + n) * KNB + l] = idx;
    }
}

// ---------------------------------------------------------------------------
// Kernel 2: Q/K SGEMM. Each block: 64 rows x 128 cols, g=0 -> Wq, g=1 -> Wk.
// ---------------------------------------------------------------------------
#define WPITCH 129
#define GEMM_SMEM ((128 * WPITCH + 64 * 128) * 4)

__global__ void __launch_bounds__(256) qk_gemm_kernel(
        const float* __restrict__ X,
        const float* __restrict__ Wq, const float* __restrict__ bq,
        const float* __restrict__ Wk, const float* __restrict__ bk) {
    extern __shared__ float sm[];
    float* sWT = sm;                   // [k=128][pitch 129] W^T
    float* sX  = sm + 128 * WPITCH;    // [64][128]

    int tid  = threadIdx.x;
    int g    = blockIdx.x & 1;
    int row0 = (blockIdx.x >> 1) * 64;
    const float* W    = g ? Wk : Wq;
    const float* bias = g ? bk : bq;

    for (int i = tid; i < 128 * 128; i += 256) {
        int e = i >> 7, d = i & 127;
        sWT[d * WPITCH + e] = W[i];
    }
    for (int i = tid; i < 64 * 128; i += 256)
        sX[i] = X[(size_t)row0 * 128 + i];
    __syncthreads();

    int w = tid >> 5, l = tid & 31;
    int rbase = w * 8;

    float acc[8][4];
    float bm[4];
#pragma unroll
    for (int m = 0; m < 4; m++) bm[m] = __ldg(&bias[l + 32 * m]);
#pragma unroll
    for (int r = 0; r < 8; r++)
#pragma unroll
        for (int m = 0; m < 4; m++) acc[r][m] = bm[m];

    const float4* sX4 = (const float4*)sX;
#pragma unroll 2
    for (int k4 = 0; k4 < 32; k4++) {
        float4 xv[8];
#pragma unroll
        for (int r = 0; r < 8; r++) xv[r] = sX4[(rbase + r) * 32 + k4];
        float wv0[4], wv1[4], wv2[4], wv3[4];
#pragma unroll
        for (int m = 0; m < 4; m++) {
            int bidx = (4 * k4) * WPITCH + l + 32 * m;
            wv0[m] = sWT[bidx];
            wv1[m] = sWT[bidx + WPITCH];
            wv2[m] = sWT[bidx + 2 * WPITCH];
            wv3[m] = sWT[bidx + 3 * WPITCH];
        }
#pragma unroll
        for (int r = 0; r < 8; r++)
#pragma unroll
            for (int m = 0; m < 4; m++) {
                float a = acc[r][m];
                a = fmaf(xv[r].x, wv0[m], a);
                a = fmaf(xv[r].y, wv1[m], a);
                a = fmaf(xv[r].z, wv2[m], a);
                a = fmaf(xv[r].w, wv3[m], a);
                acc[r][m] = a;
            }
    }

#pragma unroll
    for (int r = 0; r < 8; r++) {
        size_t orow = (size_t)(row0 + rbase + r) * 256 + g * 128;
#pragma unroll
        for (int m = 0; m < 4; m++) g_QK[orow + l + 32 * m] = acc[r][m];
    }
}

// ---------------------------------------------------------------------------
// Kernel 3: warp-cooperative scores + softmax + gather; features now fp16.
// Lane l: score chunk ch 4l..4l+3 (fp32 K), gather ch 4l..4l+3 & 128+4l..+3.
// ---------------------------------------------------------------------------
__global__ void __launch_bounds__(256) attn_kernel(float* __restrict__ out) {
    __shared__ float s_out[CCH * 33];

    int tid = threadIdx.x;
    int w = tid >> 5, l = tid & 31;
    int p0 = blockIdx.x * 32;
    int b  = p0 >> 12;

    for (int i = 0; i < 4; i++) {
        int p  = p0 + w * 4 + i;
        int nb = g_idx[p * KNB + (l & 15)];

        const float4* qv = (const float4*)(g_QK + (size_t)p * 256);
        float4 q4 = qv[l];

        float pj[KNB];
#pragma unroll
        for (int jj = 0; jj < KNB; jj++) {
            int nbj = __shfl_sync(0xffffffffu, nb, jj);
            const float4* kv = (const float4*)(g_QK + ((size_t)(b * NPTS) + nbj) * 256 + 128);
            float4 k4 = kv[l];
            pj[jj] = fmaf(q4.x, k4.x, fmaf(q4.y, k4.y, fmaf(q4.z, k4.z, q4.w * k4.w)));
        }
#pragma unroll
        for (int off = 16; off; off >>= 1)
#pragma unroll
            for (int jj = 0; jj < KNB; jj++)
                pj[jj] += __shfl_xor_sync(0xffffffffu, pj[jj], off);

        float mx = pj[0];
#pragma unroll
        for (int jj = 1; jj < KNB; jj++) mx = fmaxf(mx, pj[jj]);
        float sum = 0.f;
#pragma unroll
        for (int jj = 0; jj < KNB; jj++) {
            pj[jj] = __expf((pj[jj] - mx) * 0.08838834764831845f);
            sum += pj[jj];
        }
        float inv = 1.0f / sum;

        float4 acc0 = {0, 0, 0, 0}, acc1 = {0, 0, 0, 0};
#pragma unroll
        for (int jj = 0; jj < KNB; jj++) {
            float a = pj[jj] * inv;
            int nbj = __shfl_sync(0xffffffffu, nb, jj);
            const uint2* fv = (const uint2*)(g_featT + ((size_t)(b * NPTS) + nbj) * 256);
            uint2 u0 = fv[l];          // ch 4l..4l+3 (4 halves)
            uint2 u1 = fv[32 + l];     // ch 128+4l..128+4l+3
            float2 f00 = __half22float2(*(const __half2*)&u0.x);
            float2 f01 = __half22float2(*(const __half2*)&u0.y);
            float2 f10 = __half22float2(*(const __half2*)&u1.x);
            float2 f11 = __half22float2(*(const __half2*)&u1.y);
            acc0.x = fmaf(a, f00.x, acc0.x); acc0.y = fmaf(a, f00.y, acc0.y);
            acc0.z = fmaf(a, f01.x, acc0.z); acc0.w = fmaf(a, f01.y, acc0.w);
            acc1.x = fmaf(a, f10.x, acc1.x); acc1.y = fmaf(a, f10.y, acc1.y);
            acc1.z = fmaf(a, f11.x, acc1.z); acc1.w = fmaf(a, f11.y, acc1.w);
        }

        int pr = w * 4 + i;
        int c0 = 4 * l;
        s_out[(c0 + 0) * 33 + pr] = acc0.x;
        s_out[(c0 + 1) * 33 + pr] = acc0.y;
        s_out[(c0 + 2) * 33 + pr] = acc0.z;
        s_out[(c0 + 3) * 33 + pr] = acc0.w;
        s_out[(128 + c0 + 0) * 33 + pr] = acc1.x;
        s_out[(128 + c0 + 1) * 33 + pr] = acc1.y;
        s_out[(128 + c0 + 2) * 33 + pr] = acc1.z;
        s_out[(128 + c0 + 3) * 33 + pr] = acc1.w;
    }
    __syncthreads();

    float* obase = out + (size_t)b * CCH * NPTS;
    int n0 = p0 & (NPTS - 1);
#pragma unroll
    for (int i = 0; i < 32; i++) {
        int linear = i * 256 + tid;
        int c  = linear >> 5;
        int nl = linear & 31;
        obase[(size_t)c * NPTS + n0 + nl] = s_out[c * 33 + nl];
    }
}

// ---------------------------------------------------------------------------
extern "C" void kernel_launch(void* const* d_in, const int* in_sizes, int n_in,
                              void* d_out, int out_size) {
    const float* xyz    = (const float*)d_in[0];
    const float* feat   = (const float*)d_in[1];
    const float* concat = (const float*)d_in[2];
    const float* Wq     = (const float*)d_in[3];
    const float* bq     = (const float*)d_in[4];
    const float* Wk     = (const float*)d_in[5];
    const float* bk     = (const float*)d_in[6];
    float* out = (float*)d_out;

    cudaFuncSetAttribute(knn_kernel, cudaFuncAttributeMaxDynamicSharedMemorySize, KNN_SMEM);
    cudaFuncSetAttribute(qk_gemm_kernel, cudaFuncAttributeMaxDynamicSharedMemorySize, GEMM_SMEM);

    dim3 tgrid(CCH / 32, NPTS / 32, BATCH);
    transpose_kernel<<<tgrid, dim3(32, 8)>>>(feat);
    knn_kernel<<<BATCH * 64, KNN_BLOCK, KNN_SMEM>>>(xyz);
    qk_gemm_kernel<<<(BATCH * NPTS / 64) * 2, 256, GEMM_SMEM>>>(concat, Wq, bq, Wk, bk);
    attn_kernel<<<(BATCH * NPTS) / 32, 256>>>(out);
}

// round 9
// speedup vs baseline: 2.7260x; 1.0869x over previous
#include <cuda_runtime.h>
#include <cuda_fp16.h>
#include <cstdint>
#include <math.h>
#include <float.h>

#define BATCH 8
#define NPTS  4096
#define CCH   256
#define DD    128
#define KNB   16

__device__ float  g_QK[BATCH * NPTS * (2 * DD)];   // [p][0:128]=Q, [128:256]=K
__device__ __half g_featT[BATCH * NPTS * CCH];      // [b][n][c] fp16
__device__ int    g_idx[BATCH * NPTS * KNB];

// ---------------------------------------------------------------------------
// Kernel 0: transpose fp4_features [B,C,N] -> [B,N,C], fp32 -> fp16
// ---------------------------------------------------------------------------
__global__ void transpose_kernel(const float* __restrict__ feat) {
    __shared__ float tile[32][33];
    int b  = blockIdx.z;
    int c0 = blockIdx.x * 32;
    int n0 = blockIdx.y * 32;
    int tx = threadIdx.x, ty = threadIdx.y;
    const float* src = feat + (size_t)b * CCH * NPTS;
#pragma unroll
    for (int i = 0; i < 32; i += 8)
        tile[ty + i][tx] = src[(size_t)(c0 + ty + i) * NPTS + n0 + tx];
    __syncthreads();
    __half* dst = g_featT + (size_t)b * NPTS * CCH;
#pragma unroll
    for (int i = 0; i < 32; i += 8)
        dst[(size_t)(n0 + ty + i) * CCH + c0 + tx] = __float2half_rn(tile[tx][ty + i]);
}

// ---------------------------------------------------------------------------
// Kernel 1: KNN v6 — warp-cooperative, bitonic init, lazy threshold,
// 2 candidates per lane per iteration (one combined ballot per 64).
// ---------------------------------------------------------------------------
#define KNN_BLOCK 512
#define KNN_SMEM  (NPTS * 16)

__device__ __forceinline__ void winsert(float v, int j, float& val, int& idx, int l) {
    float upv = __shfl_up_sync(0xffffffffu, val, 1);
    int   upi = __shfl_up_sync(0xffffffffu, idx, 1);
    bool pr = (l < 16) && (val < v);
    unsigned pm = __ballot_sync(0xffffffffu, pr);
    if (pm) {
        int pos = __ffs(pm) - 1;
        if (pr) {
            val = (l == pos) ? v : upv;
            idx = (l == pos) ? j : upi;
        }
    }
}

__global__ void __launch_bounds__(KNN_BLOCK) knn_kernel(const float* __restrict__ xyz) {
    extern __shared__ float4 sp[];            // [4096] (x,y,z,|x|^2)  64KB

    int tid = threadIdx.x;
    int b     = blockIdx.x >> 6;
    int qbase = (blockIdx.x & 63) * 64;

    const float* base = xyz + (size_t)b * NPTS * 3;
    for (int i = tid; i < NPTS; i += KNN_BLOCK) {
        float x = base[i * 3 + 0], y = base[i * 3 + 1], z = base[i * 3 + 2];
        sp[i] = make_float4(x, y, z, fmaf(x, x, fmaf(y, y, z * z)));
    }
    __syncthreads();

    int w = tid >> 5, l = tid & 31;

    for (int qq = 0; qq < 4; qq++) {
        int n = qbase + w * 4 + qq;
        float4 q = sp[n];
        float qx = q.x, qy = q.y, qz = q.z, xxi = q.w;

        // seed: candidates 0..31 via full-warp bitonic sort (descending)
        float4 c0v = sp[l];
        float val = fmaf(2.0f, fmaf(qx, c0v.x, fmaf(qy, c0v.y, qz * c0v.z)), -xxi) - c0v.w;
        int   idx = l;
#pragma unroll
        for (int ksz = 2; ksz <= 32; ksz <<= 1) {
#pragma unroll
            for (int jsz = ksz >> 1; jsz > 0; jsz >>= 1) {
                float ov = __shfl_xor_sync(0xffffffffu, val, jsz);
                int   oi = __shfl_xor_sync(0xffffffffu, idx, jsz);
                bool keepBig = ((l & jsz) == 0) == ((l & ksz) == 0);
                bool take = keepBig ? (ov > val) : (ov < val);
                if (take) { val = ov; idx = oi; }
            }
        }
        float thr = __shfl_sync(0xffffffffu, val, 15);

        // candidates 32..63 (single-width iteration)
        {
            float4 c = sp[32 + l];
            float dot = fmaf(qx, c.x, fmaf(qy, c.y, qz * c.z));
            float pd  = fmaf(2.0f, dot, -xxi) - c.w;
            unsigned mask = __ballot_sync(0xffffffffu, pd > thr);
            if (mask) {
                do {
                    int s = __ffs(mask) - 1;
                    mask &= mask - 1;
                    float v = __shfl_sync(0xffffffffu, pd, s);
                    if (v > thr) winsert(v, 32 + s, val, idx, l);
                } while (mask);
                thr = __shfl_sync(0xffffffffu, val, 15);
            }
        }

        // main scan: 64 candidates/iteration, one ballot
        for (int c0 = 64; c0 < NPTS; c0 += 64) {
            float4 ca = sp[c0 + l];
            float4 cb = sp[c0 + 32 + l];
            float pd0 = fmaf(2.0f, fmaf(qx, ca.x, fmaf(qy, ca.y, qz * ca.z)), -xxi) - ca.w;
            float pd1 = fmaf(2.0f, fmaf(qx, cb.x, fmaf(qy, cb.y, qz * cb.z)), -xxi) - cb.w;

            unsigned mask = __ballot_sync(0xffffffffu, (pd0 > thr) || (pd1 > thr));
            if (mask) {
                do {
                    int s = __ffs(mask) - 1;
                    mask &= mask - 1;
                    float v0 = __shfl_sync(0xffffffffu, pd0, s);
                    float v1 = __shfl_sync(0xffffffffu, pd1, s);
                    if (v0 > thr) winsert(v0, c0 + s, val, idx, l);
                    if (v1 > thr) winsert(v1, c0 + 32 + s, val, idx, l);
                } while (mask);
                thr = __shfl_sync(0xffffffffu, val, 15);
            }
        }

        if (l < 16) g_idx[(size_t)(b * NPTS + n) * KNB + l] = idx;
    }
}

// ---------------------------------------------------------------------------
// Kernel 2: Q/K GEMM on tf32 tensor cores (mma.m16n8k8).
// Block: 64 rows x 128 cols, g=0 -> Wq, g=1 -> Wk. 8 warps; warp w owns
// cols [16w,16w+16) (2 n-tiles) x 64 rows (4 m-tiles). W kept untransposed
// (W[e][d] == col-major B fragment). Pitch 132 => conflict-free frag loads.
// ---------------------------------------------------------------------------
#define XPITCH 132
#define GEMM_SMEM ((64 * XPITCH + 128 * XPITCH) * 4)   // 101376 B

__device__ __forceinline__ float tf32r(float x) {
    uint32_t u;
    asm("cvt.rna.tf32.f32 %0, %1;" : "=r"(u) : "f"(x));
    return __uint_as_float(u);
}

__global__ void __launch_bounds__(256) qk_gemm_kernel(
        const float* __restrict__ X,
        const float* __restrict__ Wq, const float* __restrict__ bq,
        const float* __restrict__ Wk, const float* __restrict__ bk) {
    extern __shared__ float sm[];
    float* sX = sm;                    // [64][132]  (tf32-rounded)
    float* sW = sm + 64 * XPITCH;      // [128][132] W[e][d] (tf32-rounded)

    int tid  = threadIdx.x;
    int g    = blockIdx.x & 1;
    int row0 = (blockIdx.x >> 1) * 64;
    const float* W    = g ? Wk : Wq;
    const float* bias = g ? bk : bq;

    for (int i = tid; i < 128 * 128; i += 256) {
        int e = i >> 7, d = i & 127;
        sW[e * XPITCH + d] = tf32r(W[i]);
    }
    for (int i = tid; i < 64 * 128; i += 256) {
        int r = i >> 7, d = i & 127;
        sX[r * XPITCH + d] = tf32r(X[(size_t)row0 * 128 + i]);
    }
    __syncthreads();

    int w  = tid >> 5, l = tid & 31;
    int n0 = w * 16;
    int lr = l >> 2, lc = l & 3;

    float c[4][2][4];
    {
        float b0[2], b1[2];
#pragma unroll
        for (int nt = 0; nt < 2; nt++) {
            b0[nt] = __ldg(&bias[n0 + nt * 8 + 2 * lc]);
            b1[nt] = __ldg(&bias[n0 + nt * 8 + 2 * lc + 1]);
        }
#pragma unroll
        for (int mt = 0; mt < 4; mt++)
#pragma unroll
            for (int nt = 0; nt < 2; nt++) {
                c[mt][nt][0] = b0[nt]; c[mt][nt][1] = b1[nt];
                c[mt][nt][2] = b0[nt]; c[mt][nt][3] = b1[nt];
            }
    }

#pragma unroll 4
    for (int k0 = 0; k0 < 128; k0 += 8) {
        uint32_t a[4][4];
#pragma unroll
        for (int mt = 0; mt < 4; mt++) {
            int row = mt * 16 + lr;
            a[mt][0] = __float_as_uint(sX[row * XPITCH + k0 + lc]);
            a[mt][1] = __float_as_uint(sX[(row + 8) * XPITCH + k0 + lc]);
            a[mt][2] = __float_as_uint(sX[row * XPITCH + k0 + 4 + lc]);
            a[mt][3] = __float_as_uint(sX[(row + 8) * XPITCH + k0 + 4 + lc]);
        }
        uint32_t bb[2][2];
#pragma unroll
        for (int nt = 0; nt < 2; nt++) {
            int col = n0 + nt * 8 + lr;
            bb[nt][0] = __float_as_uint(sW[col * XPITCH + k0 + lc]);
            bb[nt][1] = __float_as_uint(sW[col * XPITCH + k0 + 4 + lc]);
        }
#pragma unroll
        for (int mt = 0; mt < 4; mt++)
#pragma unroll
            for (int nt = 0; nt < 2; nt++) {
                asm volatile(
                    "mma.sync.aligned.m16n8k8.row.col.f32.tf32.tf32.f32 "
                    "{%0,%1,%2,%3}, {%4,%5,%6,%7}, {%8,%9}, {%0,%1,%2,%3};"
                    : "+f"(c[mt][nt][0]), "+f"(c[mt][nt][1]),
                      "+f"(c[mt][nt][2]), "+f"(c[mt][nt][3])
                    : "r"(a[mt][0]), "r"(a[mt][1]), "r"(a[mt][2]), "r"(a[mt][3]),
                      "r"(bb[nt][0]), "r"(bb[nt][1]));
            }
    }

    // epilogue: c0/c1 -> (row, col 2lc..2lc+1), c2/c3 -> row+8
#pragma unroll
    for (int mt = 0; mt < 4; mt++) {
        int rg = row0 + mt * 16 + lr;
#pragma unroll
        for (int nt = 0; nt < 2; nt++) {
            int cg = g * 128 + n0 + nt * 8 + 2 * lc;
            float2* p0 = (float2*)&g_QK[(size_t)rg * 256 + cg];
            float2* p1 = (float2*)&g_QK[(size_t)(rg + 8) * 256 + cg];
            *p0 = make_float2(c[mt][nt][0], c[mt][nt][1]);
            *p1 = make_float2(c[mt][nt][2], c[mt][nt][3]);
        }
    }
}

// ---------------------------------------------------------------------------
// Kernel 3: warp-cooperative scores + softmax + gather; features fp16.
// ---------------------------------------------------------------------------
__global__ void __launch_bounds__(256) attn_kernel(float* __restrict__ out) {
    __shared__ float s_out[CCH * 33];

    int tid = threadIdx.x;
    int w = tid >> 5, l = tid & 31;
    int p0 = blockIdx.x * 32;
    int b  = p0 >> 12;

    for (int i = 0; i < 4; i++) {
        int p  = p0 + w * 4 + i;
        int nb = g_idx[p * KNB + (l & 15)];

        const float4* qv = (const float4*)(g_QK + (size_t)p * 256);
        float4 q4 = qv[l];

        float pj[KNB];
#pragma unroll
        for (int jj = 0; jj < KNB; jj++) {
            int nbj = __shfl_sync(0xffffffffu, nb, jj);
            const float4* kv = (const float4*)(g_QK + ((size_t)(b * NPTS) + nbj) * 256 + 128);
            float4 k4 = kv[l];
            pj[jj] = fmaf(q4.x, k4.x, fmaf(q4.y, k4.y, fmaf(q4.z, k4.z, q4.w * k4.w)));
        }
#pragma unroll
        for (int off = 16; off; off >>= 1)
#pragma unroll
            for (int jj = 0; jj < KNB; jj++)
                pj[jj] += __shfl_xor_sync(0xffffffffu, pj[jj], off);

        float mx = pj[0];
#pragma unroll
        for (int jj = 1; jj < KNB; jj++) mx = fmaxf(mx, pj[jj]);
        float sum = 0.f;
#pragma unroll
        for (int jj = 0; jj < KNB; jj++) {
            pj[jj] = __expf((pj[jj] - mx) * 0.08838834764831845f);
            sum += pj[jj];
        }
        float inv = 1.0f / sum;

        float4 acc0 = {0, 0, 0, 0}, acc1 = {0, 0, 0, 0};
#pragma unroll
        for (int jj = 0; jj < KNB; jj++) {
            float a = pj[jj] * inv;
            int nbj = __shfl_sync(0xffffffffu, nb, jj);
            const uint2* fv = (const uint2*)(g_featT + ((size_t)(b * NPTS) + nbj) * 256);
            uint2 u0 = fv[l];
            uint2 u1 = fv[32 + l];
            float2 f00 = __half22float2(*(const __half2*)&u0.x);
            float2 f01 = __half22float2(*(const __half2*)&u0.y);
            float2 f10 = __half22float2(*(const __half2*)&u1.x);
            float2 f11 = __half22float2(*(const __half2*)&u1.y);
            acc0.x = fmaf(a, f00.x, acc0.x); acc0.y = fmaf(a, f00.y, acc0.y);
            acc0.z = fmaf(a, f01.x, acc0.z); acc0.w = fmaf(a, f01.y, acc0.w);
            acc1.x = fmaf(a, f10.x, acc1.x); acc1.y = fmaf(a, f10.y, acc1.y);
            acc1.z = fmaf(a, f11.x, acc1.z); acc1.w = fmaf(a, f11.y, acc1.w);
        }

        int pr = w * 4 + i;
        int c0 = 4 * l;
        s_out[(c0 + 0) * 33 + pr] = acc0.x;
        s_out[(c0 + 1) * 33 + pr] = acc0.y;
        s_out[(c0 + 2) * 33 + pr] = acc0.z;
        s_out[(c0 + 3) * 33 + pr] = acc0.w;
        s_out[(128 + c0 + 0) * 33 + pr] = acc1.x;
        s_out[(128 + c0 + 1) * 33 + pr] = acc1.y;
        s_out[(128 + c0 + 2) * 33 + pr] = acc1.z;
        s_out[(128 + c0 + 3) * 33 + pr] = acc1.w;
    }
    __syncthreads();

    float* obase = out + (size_t)b * CCH * NPTS;
    int n0 = p0 & (NPTS - 1);
#pragma unroll
    for (int i = 0; i < 32; i++) {
        int linear = i * 256 + tid;
        int c  = linear >> 5;
        int nl = linear & 31;
        obase[(size_t)c * NPTS + n0 + nl] = s_out[c * 33 + nl];
    }
}

// ---------------------------------------------------------------------------
extern "C" void kernel_launch(void* const* d_in, const int* in_sizes, int n_in,
                              void* d_out, int out_size) {
    const float* xyz    = (const float*)d_in[0];
    const float* feat   = (const float*)d_in[1];
    const float* concat = (const float*)d_in[2];
    const float* Wq     = (const float*)d_in[3];
    const float* bq     = (const float*)d_in[4];
    const float* Wk     = (const float*)d_in[5];
    const float* bk     = (const float*)d_in[6];
    float* out = (float*)d_out;

    cudaFuncSetAttribute(knn_kernel, cudaFuncAttributeMaxDynamicSharedMemorySize, KNN_SMEM);
    cudaFuncSetAttribute(qk_gemm_kernel, cudaFuncAttributeMaxDynamicSharedMemorySize, GEMM_SMEM);

    dim3 tgrid(CCH / 32, NPTS / 32, BATCH);
    transpose_kernel<<<tgrid, dim3(32, 8)>>>(feat);
    knn_kernel<<<BATCH * 64, KNN_BLOCK, KNN_SMEM>>>(xyz);
    qk_gemm_kernel<<<(BATCH * NPTS / 64) * 2, 256, GEMM_SMEM>>>(concat, Wq, bq, Wk, bk);
    attn_kernel<<<(BATCH * NPTS) / 32, 256>>>(out);
}

// round 10
// speedup vs baseline: 2.8279x; 1.0374x over previous
#include <cuda_runtime.h>
#include <cuda_fp16.h>
#include <cstdint>
#include <math.h>
#include <float.h>

#define BATCH 8
#define NPTS  4096
#define CCH   256
#define DD    128
#define KNB   16

__device__ float  g_QK[BATCH * NPTS * (2 * DD)];   // [p][0:128]=Q, [128:256]=K
__device__ __half g_featT[BATCH * NPTS * CCH];      // [b][n][c] fp16
__device__ int    g_idx[BATCH * NPTS * KNB];

// ---------------------------------------------------------------------------
// Kernel 0: transpose fp4_features [B,C,N] -> [B,N,C], fp32 -> fp16
// ---------------------------------------------------------------------------
__global__ void transpose_kernel(const float* __restrict__ feat) {
    __shared__ float tile[32][33];
    int b  = blockIdx.z;
    int c0 = blockIdx.x * 32;
    int n0 = blockIdx.y * 32;
    int tx = threadIdx.x, ty = threadIdx.y;
    const float* src = feat + (size_t)b * CCH * NPTS;
#pragma unroll
    for (int i = 0; i < 32; i += 8)
        tile[ty + i][tx] = src[(size_t)(c0 + ty + i) * NPTS + n0 + tx];
    __syncthreads();
    __half* dst = g_featT + (size_t)b * NPTS * CCH;
#pragma unroll
    for (int i = 0; i < 32; i += 8)
        dst[(size_t)(n0 + ty + i) * CCH + c0 + tx] = __float2half_rn(tile[tx][ty + i]);
}

// ---------------------------------------------------------------------------
// Kernel 1: KNN v7 — 2 queries per warp, segmented top-16 lists.
// Lanes 0-15: query A's sorted list (descending); lanes 16-31: query B's.
// One LDS.128 / 32 candidates / iteration serves BOTH queries; the insert
// (shfl_up width 16 + split ballot) updates both lists in one shared sequence.
// ---------------------------------------------------------------------------
#define KNN_BLOCK 512
#define KNN_SMEM  (NPTS * 16)

__global__ void __launch_bounds__(KNN_BLOCK) knn_kernel(const float* __restrict__ xyz) {
    extern __shared__ float4 sp[];            // [4096] (x,y,z,|x|^2)  64KB

    int tid = threadIdx.x;
    int b     = blockIdx.x >> 6;
    int qbase = (blockIdx.x & 63) * 64;

    const float* base = xyz + (size_t)b * NPTS * 3;
    for (int i = tid; i < NPTS; i += KNN_BLOCK) {
        float x = base[i * 3 + 0], y = base[i * 3 + 1], z = base[i * 3 + 2];
        sp[i] = make_float4(x, y, z, fmaf(x, x, fmaf(y, y, z * z)));
    }
    __syncthreads();

    int w   = tid >> 5, l = tid & 31;
    int seg = l >> 4;            // 0 = query A, 1 = query B
    int sl  = l & 15;            // lane within segment

    for (int pass = 0; pass < 2; pass++) {
        int nA = qbase + w * 4 + pass * 2;
        int nB = nA + 1;
        float4 qa = sp[nA];
        float4 qb = sp[nB];
        float qax = qa.x, qay = qa.y, qaz = qa.z, qaxx = qa.w;
        float qbx = qb.x, qby = qb.y, qbz = qb.z, qbxx = qb.w;

        // --- seed: candidates 0..15 into each segment's list, segmented sort ---
        float4 cs = sp[sl];
        float mqx = seg ? qbx : qax, mqy = seg ? qby : qay;
        float mqz = seg ? qbz : qaz, mxx = seg ? qbxx : qaxx;
        float val = fmaf(2.0f, fmaf(mqx, cs.x, fmaf(mqy, cs.y, mqz * cs.z)), -mxx) - cs.w;
        int   idx = sl;
#pragma unroll
        for (int ksz = 2; ksz <= 16; ksz <<= 1) {
#pragma unroll
            for (int jsz = ksz >> 1; jsz > 0; jsz >>= 1) {
                float ov = __shfl_xor_sync(0xffffffffu, val, jsz, 16);
                int   oi = __shfl_xor_sync(0xffffffffu, idx, jsz, 16);
                bool keepBig = ((sl & jsz) == 0) == ((sl & ksz) == 0);
                bool take = keepBig ? (ov > val) : (ov < val);
                if (take) { val = ov; idx = oi; }
            }
        }
        float thrA = __shfl_sync(0xffffffffu, val, 15);
        float thrB = __shfl_sync(0xffffffffu, val, 31);

        // --- special window: candidates 16..31, each segment evaluates its own ---
        {
            float4 c = sp[16 + sl];
            float pd = fmaf(2.0f, fmaf(mqx, c.x, fmaf(mqy, c.y, mqz * c.z)), -mxx) - c.w;
            float mythr = seg ? thrB : thrA;
            unsigned mask = __ballot_sync(0xffffffffu, pd > mythr);
            while (mask) {
                int s = __ffs(mask) - 1;
                mask &= mask - 1;
                int sseg = s >> 4;
                float v = __shfl_sync(0xffffffffu, pd, s);
                float myv = (seg == sseg) ? v : -FLT_MAX;
                int j = 16 + (s & 15);
                float upv = __shfl_up_sync(0xffffffffu, val, 1, 16);
                int   upi = __shfl_up_sync(0xffffffffu, idx, 1, 16);
                bool pr = val < myv;
                unsigned pm = __ballot_sync(0xffffffffu, pr);
                unsigned pmseg = seg ? (pm >> 16) : (pm & 0xFFFFu);
                int pos = __ffs(pmseg) - 1;
                if (pr) {
                    val = (sl == pos) ? myv : upv;
                    idx = (sl == pos) ? j : upi;
                }
            }
            thrA = __shfl_sync(0xffffffffu, val, 15);
            thrB = __shfl_sync(0xffffffffu, val, 31);
        }

        // --- main scan: candidates 32..4095, 32 per iteration, both queries ---
        for (int c0 = 32; c0 < NPTS; c0 += 32) {
            float4 c = sp[c0 + l];
            float pdA = fmaf(2.0f, fmaf(qax, c.x, fmaf(qay, c.y, qaz * c.z)), -qaxx) - c.w;
            float pdB = fmaf(2.0f, fmaf(qbx, c.x, fmaf(qby, c.y, qbz * c.z)), -qbxx) - c.w;

            unsigned mask = __ballot_sync(0xffffffffu, (pdA > thrA) || (pdB > thrB));
            if (mask) {
                do {
                    int s = __ffs(mask) - 1;
                    mask &= mask - 1;
                    float vA = __shfl_sync(0xffffffffu, pdA, s);
                    float vB = __shfl_sync(0xffffffffu, pdB, s);
                    float myv = seg ? vB : vA;
                    int j = c0 + s;
                    // shared segmented insert (no-op for a segment if myv <= its min)
                    float upv = __shfl_up_sync(0xffffffffu, val, 1, 16);
                    int   upi = __shfl_up_sync(0xffffffffu, idx, 1, 16);
                    bool pr = val < myv;
                    unsigned pm = __ballot_sync(0xffffffffu, pr);
                    unsigned pmseg = seg ? (pm >> 16) : (pm & 0xFFFFu);
                    int pos = __ffs(pmseg) - 1;
                    if (pr) {
                        val = (sl == pos) ? myv : upv;
                        idx = (sl == pos) ? j : upi;
                    }
                } while (mask);
                thrA = __shfl_sync(0xffffffffu, val, 15);
                thrB = __shfl_sync(0xffffffffu, val, 31);
            }
        }

        int nq = seg ? nB : nA;
        g_idx[(size_t)(b * NPTS + nq) * KNB + sl] = idx;
    }
}

// ---------------------------------------------------------------------------
// Kernel 2: Q/K GEMM on tf32 tensor cores (mma.m16n8k8). Unchanged from R9.
// ---------------------------------------------------------------------------
#define XPITCH 132
#define GEMM_SMEM ((64 * XPITCH + 128 * XPITCH) * 4)   // 101376 B

__device__ __forceinline__ float tf32r(float x) {
    uint32_t u;
    asm("cvt.rna.tf32.f32 %0, %1;" : "=r"(u) : "f"(x));
    return __uint_as_float(u);
}

__global__ void __launch_bounds__(256) qk_gemm_kernel(
        const float* __restrict__ X,
        const float* __restrict__ Wq, const float* __restrict__ bq,
        const float* __restrict__ Wk, const float* __restrict__ bk) {
    extern __shared__ float sm[];
    float* sX = sm;                    // [64][132]  (tf32-rounded)
    float* sW = sm + 64 * XPITCH;      // [128][132] W[e][d] (tf32-rounded)

    int tid  = threadIdx.x;
    int g    = blockIdx.x & 1;
    int row0 = (blockIdx.x >> 1) * 64;
    const float* W    = g ? Wk : Wq;
    const float* bias = g ? bk : bq;

    for (int i = tid; i < 128 * 128; i += 256) {
        int e = i >> 7, d = i & 127;
        sW[e * XPITCH + d] = tf32r(W[i]);
    }
    for (int i = tid; i < 64 * 128; i += 256) {
        int r = i >> 7, d = i & 127;
        sX[r * XPITCH + d] = tf32r(X[(size_t)row0 * 128 + i]);
    }
    __syncthreads();

    int w  = tid >> 5, l = tid & 31;
    int n0 = w * 16;
    int lr = l >> 2, lc = l & 3;

    float c[4][2][4];
    {
        float b0[2], b1[2];
#pragma unroll
        for (int nt = 0; nt < 2; nt++) {
            b0[nt] = __ldg(&bias[n0 + nt * 8 + 2 * lc]);
            b1[nt] = __ldg(&bias[n0 + nt * 8 + 2 * lc + 1]);
        }
#pragma unroll
        for (int mt = 0; mt < 4; mt++)
#pragma unroll
            for (int nt = 0; nt < 2; nt++) {
                c[mt][nt][0] = b0[nt]; c[mt][nt][1] = b1[nt];
                c[mt][nt][2] = b0[nt]; c[mt][nt][3] = b1[nt];
            }
    }

#pragma unroll 4
    for (int k0 = 0; k0 < 128; k0 += 8) {
        uint32_t a[4][4];
#pragma unroll
        for (int mt = 0; mt < 4; mt++) {
            int row = mt * 16 + lr;
            a[mt][0] = __float_as_uint(sX[row * XPITCH + k0 + lc]);
            a[mt][1] = __float_as_uint(sX[(row + 8) * XPITCH + k0 + lc]);
            a[mt][2] = __float_as_uint(sX[row * XPITCH + k0 + 4 + lc]);
            a[mt][3] = __float_as_uint(sX[(row + 8) * XPITCH + k0 + 4 + lc]);
        }
        uint32_t bb[2][2];
#pragma unroll
        for (int nt = 0; nt < 2; nt++) {
            int col = n0 + nt * 8 + lr;
            bb[nt][0] = __float_as_uint(sW[col * XPITCH + k0 + lc]);
            bb[nt][1] = __float_as_uint(sW[col * XPITCH + k0 + 4 + lc]);
        }
#pragma unroll
        for (int mt = 0; mt < 4; mt++)
#pragma unroll
            for (int nt = 0; nt < 2; nt++) {
                asm volatile(
                    "mma.sync.aligned.m16n8k8.row.col.f32.tf32.tf32.f32 "
                    "{%0,%1,%2,%3}, {%4,%5,%6,%7}, {%8,%9}, {%0,%1,%2,%3};"
                    : "+f"(c[mt][nt][0]), "+f"(c[mt][nt][1]),
                      "+f"(c[mt][nt][2]), "+f"(c[mt][nt][3])
                    : "r"(a[mt][0]), "r"(a[mt][1]), "r"(a[mt][2]), "r"(a[mt][3]),
                      "r"(bb[nt][0]), "r"(bb[nt][1]));
            }
    }

#pragma unroll
    for (int mt = 0; mt < 4; mt++) {
        int rg = row0 + mt * 16 + lr;
#pragma unroll
        for (int nt = 0; nt < 2; nt++) {
            int cg = g * 128 + n0 + nt * 8 + 2 * lc;
            float2* p0 = (float2*)&g_QK[(size_t)rg * 256 + cg];
            float2* p1 = (float2*)&g_QK[(size_t)(rg + 8) * 256 + cg];
            *p0 = make_float2(c[mt][nt][0], c[mt][nt][1]);
            *p1 = make_float2(c[mt][nt][2], c[mt][nt][3]);
        }
    }
}

// ---------------------------------------------------------------------------
// Kernel 3: warp-cooperative scores + softmax + gather; features fp16.
// ---------------------------------------------------------------------------
__global__ void __launch_bounds__(256) attn_kernel(float* __restrict__ out) {
    __shared__ float s_out[CCH * 33];

    int tid = threadIdx.x;
    int w = tid >> 5, l = tid & 31;
    int p0 = blockIdx.x * 32;
    int b  = p0 >> 12;

    for (int i = 0; i < 4; i++) {
        int p  = p0 + w * 4 + i;
        int nb = g_idx[p * KNB + (l & 15)];

        const float4* qv = (const float4*)(g_QK + (size_t)p * 256);
        float4 q4 = qv[l];

        float pj[KNB];
#pragma unroll
        for (int jj = 0; jj < KNB; jj++) {
            int nbj = __shfl_sync(0xffffffffu, nb, jj);
            const float4* kv = (const float4*)(g_QK + ((size_t)(b * NPTS) + nbj) * 256 + 128);
            float4 k4 = kv[l];
            pj[jj] = fmaf(q4.x, k4.x, fmaf(q4.y, k4.y, fmaf(q4.z, k4.z, q4.w * k4.w)));
        }
#pragma unroll
        for (int off = 16; off; off >>= 1)
#pragma unroll
            for (int jj = 0; jj < KNB; jj++)
                pj[jj] += __shfl_xor_sync(0xffffffffu, pj[jj], off);

        float mx = pj[0];
#pragma unroll
        for (int jj = 1; jj < KNB; jj++) mx = fmaxf(mx, pj[jj]);
        float sum = 0.f;
#pragma unroll
        for (int jj = 0; jj < KNB; jj++) {
            pj[jj] = __expf((pj[jj] - mx) * 0.08838834764831845f);
            sum += pj[jj];
        }
        float inv = 1.0f / sum;

        float4 acc0 = {0, 0, 0, 0}, acc1 = {0, 0, 0, 0};
#pragma unroll
        for (int jj = 0; jj < KNB; jj++) {
            float a = pj[jj] * inv;
            int nbj = __shfl_sync(0xffffffffu, nb, jj);
            const uint2* fv = (const uint2*)(g_featT + ((size_t)(b * NPTS) + nbj) * 256);
            uint2 u0 = fv[l];
            uint2 u1 = fv[32 + l];
            float2 f00 = __half22float2(*(const __half2*)&u0.x);
            float2 f01 = __half22float2(*(const __half2*)&u0.y);
            float2 f10 = __half22float2(*(const __half2*)&u1.x);
            float2 f11 = __half22float2(*(const __half2*)&u1.y);
            acc0.x = fmaf(a, f00.x, acc0.x); acc0.y = fmaf(a, f00.y, acc0.y);
            acc0.z = fmaf(a, f01.x, acc0.z); acc0.w = fmaf(a, f01.y, acc0.w);
            acc1.x = fmaf(a, f10.x, acc1.x); acc1.y = fmaf(a, f10.y, acc1.y);
            acc1.z = fmaf(a, f11.x, acc1.z); acc1.w = fmaf(a, f11.y, acc1.w);
        }

        int pr = w * 4 + i;
        int c0 = 4 * l;
        s_out[(c0 + 0) * 33 + pr] = acc0.x;
        s_out[(c0 + 1) * 33 + pr] = acc0.y;
        s_out[(c0 + 2) * 33 + pr] = acc0.z;
        s_out[(c0 + 3) * 33 + pr] = acc0.w;
        s_out[(128 + c0 + 0) * 33 + pr] = acc1.x;
        s_out[(128 + c0 + 1) * 33 + pr] = acc1.y;
        s_out[(128 + c0 + 2) * 33 + pr] = acc1.z;
        s_out[(128 + c0 + 3) * 33 + pr] = acc1.w;
    }
    __syncthreads();

    float* obase = out + (size_t)b * CCH * NPTS;
    int n0 = p0 & (NPTS - 1);
#pragma unroll
    for (int i = 0; i < 32; i++) {
        int linear = i * 256 + tid;
        int c  = linear >> 5;
        int nl = linear & 31;
        obase[(size_t)c * NPTS + n0 + nl] = s_out[c * 33 + nl];
    }
}

// ---------------------------------------------------------------------------
extern "C" void kernel_launch(void* const* d_in, const int* in_sizes, int n_in,
                              void* d_out, int out_size) {
    const float* xyz    = (const float*)d_in[0];
    const float* feat   = (const float*)d_in[1];
    const float* concat = (const float*)d_in[2];
    const float* Wq     = (const float*)d_in[3];
    const float* bq     = (const float*)d_in[4];
    const float* Wk     = (const float*)d_in[5];
    const float* bk     = (const float*)d_in[6];
    float* out = (float*)d_out;

    cudaFuncSetAttribute(knn_kernel, cudaFuncAttributeMaxDynamicSharedMemorySize, KNN_SMEM);
    cudaFuncSetAttribute(qk_gemm_kernel, cudaFuncAttributeMaxDynamicSharedMemorySize, GEMM_SMEM);

    dim3 tgrid(CCH / 32, NPTS / 32, BATCH);
    transpose_kernel<<<tgrid, dim3(32, 8)>>>(feat);
    knn_kernel<<<BATCH * 64, KNN_BLOCK, KNN_SMEM>>>(xyz);
    qk_gemm_kernel<<<(BATCH * NPTS / 64) * 2, 256, GEMM_SMEM>>>(concat, Wq, bq, Wk, bk);
    attn_kernel<<<(BATCH * NPTS) / 32, 256>>>(out);
}

// round 13
// speedup vs baseline: 3.5029x; 1.2387x over previous
#include <cuda_runtime.h>
#include <cuda_fp16.h>
#include <cstdint>
#include <math.h>
#include <float.h>

#define BATCH 8
#define NPTS  4096
#define CCH   256
#define DD    128
#define KNB   16

__device__ float  g_QK[BATCH * NPTS * (2 * DD)];   // [p][0:128]=Q, [128:256]=K
__device__ __half g_featT[BATCH * NPTS * CCH];      // [b][n][c] fp16
__device__ int    g_idx[BATCH * NPTS * KNB];

// ---------------------------------------------------------------------------
// Kernel 0: transpose fp4_features [B,C,N] -> [B,N,C], fp32 -> fp16
// ---------------------------------------------------------------------------
__global__ void transpose_kernel(const float* __restrict__ feat) {
    __shared__ float tile[32][33];
    int b  = blockIdx.z;
    int c0 = blockIdx.x * 32;
    int n0 = blockIdx.y * 32;
    int tx = threadIdx.x, ty = threadIdx.y;
    const float* src = feat + (size_t)b * CCH * NPTS;
#pragma unroll
    for (int i = 0; i < 32; i += 8)
        tile[ty + i][tx] = src[(size_t)(c0 + ty + i) * NPTS + n0 + tx];
    __syncthreads();
    __half* dst = g_featT + (size_t)b * NPTS * CCH;
#pragma unroll
    for (int i = 0; i < 32; i += 8)
        dst[(size_t)(n0 + ty + i) * CCH + c0 + tx] = __float2half_rn(tile[tx][ty + i]);
}

// ---------------------------------------------------------------------------
// Kernel 1: KNN v9 — threshold-first with the EXACT R10 scoring expression:
//   sp.w = |x|^2;  dot = fmaf(qx,cx,fmaf(qy,cy,qz*cz));
//   pd  = fmaf(2, dot, -xxi) - c.w
// P1: per-lane max over a private 128-candidate stream (no warp ops);
//     tau = 16th-largest of the 32 stream maxima (valid lower bound).
// P2: collect all candidates with pd >= tau into smem (expected ~22).
// P3: bitonic sort 32 -> exact top-16 (winsert fallback if cnt > 32).
// ---------------------------------------------------------------------------
#define KNN_BLOCK 512
#define SP_BYTES   (NPTS * 16)                    // 65536
#define CV_BYTES   (16 * 2 * 128 * 4)             // 16384
#define CI_BYTES   (16 * 2 * 128 * 4)             // 16384
#define KNN_SMEM   (SP_BYTES + CV_BYTES + CI_BYTES + 16 * 2 * 4)   // 98688

__device__ __forceinline__ void winsert(float v, int j, float& val, int& idx, int l) {
    float upv = __shfl_up_sync(0xffffffffu, val, 1);
    int   upi = __shfl_up_sync(0xffffffffu, idx, 1);
    bool pr = (l < 16) && (val < v);
    unsigned pm = __ballot_sync(0xffffffffu, pr);
    if (pm) {
        int pos = __ffs(pm) - 1;
        if (pr) {
            val = (l == pos) ? v : upv;
            idx = (l == pos) ? j : upi;
        }
    }
}

// descending bitonic sort of 32 values (+carried index) across a warp
__device__ __forceinline__ void bsort32(float& val, int& idx, int l) {
#pragma unroll
    for (int ksz = 2; ksz <= 32; ksz <<= 1) {
#pragma unroll
        for (int jsz = ksz >> 1; jsz > 0; jsz >>= 1) {
            float ov = __shfl_xor_sync(0xffffffffu, val, jsz);
            int   oi = __shfl_xor_sync(0xffffffffu, idx, jsz);
            bool keepBig = ((l & jsz) == 0) == ((l & ksz) == 0);
            bool take = keepBig ? (ov > val) : (ov < val);
            if (take) { val = ov; idx = oi; }
        }
    }
}

__device__ __forceinline__ float bsort32_val(float val, int l) {
#pragma unroll
    for (int ksz = 2; ksz <= 32; ksz <<= 1) {
#pragma unroll
        for (int jsz = ksz >> 1; jsz > 0; jsz >>= 1) {
            float ov = __shfl_xor_sync(0xffffffffu, val, jsz);
            bool keepBig = ((l & jsz) == 0) == ((l & ksz) == 0);
            bool take = keepBig ? (ov > val) : (ov < val);
            if (take) val = ov;
        }
    }
    return val;
}

__global__ void __launch_bounds__(KNN_BLOCK) knn_kernel(const float* __restrict__ xyz) {
    extern __shared__ char smem_raw[];
    float4* sp   = (float4*)smem_raw;                       // [4096] (x,y,z,|x|^2)
    float*  cval = (float*)(smem_raw + SP_BYTES);           // [16 warps][2 q][128]
    int*    cidx = (int*)(smem_raw + SP_BYTES + CV_BYTES);  // [16 warps][2 q][128]
    int*    ccnt = (int*)(smem_raw + SP_BYTES + CV_BYTES + CI_BYTES); // [16][2]

    int tid = threadIdx.x;
    int b     = blockIdx.x >> 6;
    int qbase = (blockIdx.x & 63) * 64;

    const float* base = xyz + (size_t)b * NPTS * 3;
    for (int i = tid; i < NPTS; i += KNN_BLOCK) {
        float x = base[i * 3 + 0], y = base[i * 3 + 1], z = base[i * 3 + 2];
        sp[i] = make_float4(x, y, z, fmaf(x, x, fmaf(y, y, z * z)));
    }
    __syncthreads();

    int w = tid >> 5, l = tid & 31;
    int lbase0 = (w * 2 + 0) * 128;
    int lbase1 = (w * 2 + 1) * 128;

    for (int pass = 0; pass < 2; pass++) {
        int nA = qbase + w * 4 + pass * 2;
        int nB = nA + 1;
        float4 qa = sp[nA];
        float4 qb = sp[nB];

        // --- P1: per-lane max over stride-32 stream (no warp ops) ---
        float mA = -FLT_MAX, mB = -FLT_MAX;
        for (int c0 = l; c0 < NPTS; c0 += 32) {
            float4 c = sp[c0];
            float dotA = fmaf(qa.x, c.x, fmaf(qa.y, c.y, qa.z * c.z));
            float dotB = fmaf(qb.x, c.x, fmaf(qb.y, c.y, qb.z * c.z));
            float pdA  = fmaf(2.0f, dotA, -qa.w) - c.w;
            float pdB  = fmaf(2.0f, dotB, -qb.w) - c.w;
            mA = fmaxf(mA, pdA);
            mB = fmaxf(mB, pdB);
        }
        float tauA = __shfl_sync(0xffffffffu, bsort32_val(mA, l), 15);
        float tauB = __shfl_sync(0xffffffffu, bsort32_val(mB, l), 15);

        if (l == 0) { ccnt[w * 2] = 0; ccnt[w * 2 + 1] = 0; }
        __syncwarp();

        // --- P2: collect candidates >= tau (rare pushes) ---
        for (int c0 = l; c0 < NPTS; c0 += 32) {
            float4 c = sp[c0];
            float dotA = fmaf(qa.x, c.x, fmaf(qa.y, c.y, qa.z * c.z));
            float dotB = fmaf(qb.x, c.x, fmaf(qb.y, c.y, qb.z * c.z));
            float pdA  = fmaf(2.0f, dotA, -qa.w) - c.w;
            float pdB  = fmaf(2.0f, dotB, -qb.w) - c.w;
            if (pdA >= tauA) {
                int s = atomicAdd(&ccnt[w * 2], 1);
                if (s < 128) { cval[lbase0 + s] = pdA; cidx[lbase0 + s] = c0; }
            }
            if (pdB >= tauB) {
                int s = atomicAdd(&ccnt[w * 2 + 1], 1);
                if (s < 128) { cval[lbase1 + s] = pdB; cidx[lbase1 + s] = c0; }
            }
        }
        __syncwarp();

        // --- P3: exact top-16 among collected, per query ---
#pragma unroll
        for (int q = 0; q < 2; q++) {
            int lb  = q ? lbase1 : lbase0;
            int cnt = min(ccnt[w * 2 + q], 128);
            float val = (l < cnt) ? cval[lb + l] : -FLT_MAX;
            int   idx = (l < cnt) ? cidx[lb + l] : 0;
            bsort32(val, idx, l);

            if (cnt > 32) {
                float thr = __shfl_sync(0xffffffffu, val, 15);
                for (int c0 = 32; c0 < cnt; c0 += 32) {
                    float pv = (c0 + l < cnt) ? cval[lb + c0 + l] : -FLT_MAX;
                    int   pi = (c0 + l < cnt) ? cidx[lb + c0 + l] : 0;
                    unsigned mask = __ballot_sync(0xffffffffu, pv > thr);
                    while (mask) {
                        int s = __ffs(mask) - 1;
                        mask &= mask - 1;
                        float v = __shfl_sync(0xffffffffu, pv, s);
                        int   j = __shfl_sync(0xffffffffu, pi, s);
                        if (v > thr) winsert(v, j, val, idx, l);
                    }
                    thr = __shfl_sync(0xffffffffu, val, 15);
                }
            }

            int n = q ? nB : nA;
            if (l < 16) g_idx[(size_t)(b * NPTS + n) * KNB + l] = idx;
        }
        __syncwarp();
    }
}

// ---------------------------------------------------------------------------
// Kernel 2: Q/K GEMM on tf32 tensor cores (mma.m16n8k8). Unchanged.
// ---------------------------------------------------------------------------
#define XPITCH 132
#define GEMM_SMEM ((64 * XPITCH + 128 * XPITCH) * 4)   // 101376 B

__device__ __forceinline__ float tf32r(float x) {
    uint32_t u;
    asm("cvt.rna.tf32.f32 %0, %1;" : "=r"(u) : "f"(x));
    return __uint_as_float(u);
}

__global__ void __launch_bounds__(256) qk_gemm_kernel(
        const float* __restrict__ X,
        const float* __restrict__ Wq, const float* __restrict__ bq,
        const float* __restrict__ Wk, const float* __restrict__ bk) {
    extern __shared__ float sm[];
    float* sX = sm;                    // [64][132]
    float* sW = sm + 64 * XPITCH;      // [128][132] W[e][d]

    int tid  = threadIdx.x;
    int g    = blockIdx.x & 1;
    int row0 = (blockIdx.x >> 1) * 64;
    const float* W    = g ? Wk : Wq;
    const float* bias = g ? bk : bq;

    for (int i = tid; i < 128 * 128; i += 256) {
        int e = i >> 7, d = i & 127;
        sW[e * XPITCH + d] = tf32r(W[i]);
    }
    for (int i = tid; i < 64 * 128; i += 256) {
        int r = i >> 7, d = i & 127;
        sX[r * XPITCH + d] = tf32r(X[(size_t)row0 * 128 + i]);
    }
    __syncthreads();

    int w  = tid >> 5, l = tid & 31;
    int n0 = w * 16;
    int lr = l >> 2, lc = l & 3;

    float c[4][2][4];
    {
        float b0[2], b1[2];
#pragma unroll
        for (int nt = 0; nt < 2; nt++) {
            b0[nt] = __ldg(&bias[n0 + nt * 8 + 2 * lc]);
            b1[nt] = __ldg(&bias[n0 + nt * 8 + 2 * lc + 1]);
        }
#pragma unroll
        for (int mt = 0; mt < 4; mt++)
#pragma unroll
            for (int nt = 0; nt < 2; nt++) {
                c[mt][nt][0] = b0[nt]; c[mt][nt][1] = b1[nt];
                c[mt][nt][2] = b0[nt]; c[mt][nt][3] = b1[nt];
            }
    }

#pragma unroll 4
    for (int k0 = 0; k0 < 128; k0 += 8) {
        uint32_t a[4][4];
#pragma unroll
        for (int mt = 0; mt < 4; mt++) {
            int row = mt * 16 + lr;
            a[mt][0] = __float_as_uint(sX[row * XPITCH + k0 + lc]);
            a[mt][1] = __float_as_uint(sX[(row + 8) * XPITCH + k0 + lc]);
            a[mt][2] = __float_as_uint(sX[row * XPITCH + k0 + 4 + lc]);
            a[mt][3] = __float_as_uint(sX[(row + 8) * XPITCH + k0 + 4 + lc]);
        }
        uint32_t bb[2][2];
#pragma unroll
        for (int nt = 0; nt < 2; nt++) {
            int col = n0 + nt * 8 + lr;
            bb[nt][0] = __float_as_uint(sW[col * XPITCH + k0 + lc]);
            bb[nt][1] = __float_as_uint(sW[col * XPITCH + k0 + 4 + lc]);
        }
#pragma unroll
        for (int mt = 0; mt < 4; mt++)
#pragma unroll
            for (int nt = 0; nt < 2; nt++) {
                asm volatile(
                    "mma.sync.aligned.m16n8k8.row.col.f32.tf32.tf32.f32 "
                    "{%0,%1,%2,%3}, {%4,%5,%6,%7}, {%8,%9}, {%0,%1,%2,%3};"
                    : "+f"(c[mt][nt][0]), "+f"(c[mt][nt][1]),
                      "+f"(c[mt][nt][2]), "+f"(c[mt][nt][3])
                    : "r"(a[mt][0]), "r"(a[mt][1]), "r"(a[mt][2]), "r"(a[mt][3]),
                      "r"(bb[nt][0]), "r"(bb[nt][1]));
            }
    }

#pragma unroll
    for (int mt = 0; mt < 4; mt++) {
        int rg = row0 + mt * 16 + lr;
#pragma unroll
        for (int nt = 0; nt < 2; nt++) {
            int cg = g * 128 + n0 + nt * 8 + 2 * lc;
            float2* p0 = (float2*)&g_QK[(size_t)rg * 256 + cg];
            float2* p1 = (float2*)&g_QK[(size_t)(rg + 8) * 256 + cg];
            *p0 = make_float2(c[mt][nt][0], c[mt][nt][1]);
            *p1 = make_float2(c[mt][nt][2], c[mt][nt][3]);
        }
    }
}

// ---------------------------------------------------------------------------
// Kernel 3: warp-cooperative scores + softmax + gather; features fp16.
// ---------------------------------------------------------------------------
__global__ void __launch_bounds__(256) attn_kernel(float* __restrict__ out) {
    __shared__ float s_out[CCH * 33];

    int tid = threadIdx.x;
    int w = tid >> 5, l = tid & 31;
    int p0 = blockIdx.x * 32;
    int b  = p0 >> 12;

    for (int i = 0; i < 4; i++) {
        int p  = p0 + w * 4 + i;
        int nb = g_idx[p * KNB + (l & 15)];

        const float4* qv = (const float4*)(g_QK + (size_t)p * 256);
        float4 q4 = qv[l];

        float pj[KNB];
#pragma unroll
        for (int jj = 0; jj < KNB; jj++) {
            int nbj = __shfl_sync(0xffffffffu, nb, jj);
            const float4* kv = (const float4*)(g_QK + ((size_t)(b * NPTS) + nbj) * 256 + 128);
            float4 k4 = kv[l];
            pj[jj] = fmaf(q4.x, k4.x, fmaf(q4.y, k4.y, fmaf(q4.z, k4.z, q4.w * k4.w)));
        }
#pragma unroll
        for (int off = 16; off; off >>= 1)
#pragma unroll
            for (int jj = 0; jj < KNB; jj++)
                pj[jj] += __shfl_xor_sync(0xffffffffu, pj[jj], off);

        float mx = pj[0];
#pragma unroll
        for (int jj = 1; jj < KNB; jj++) mx = fmaxf(mx, pj[jj]);
        float sum = 0.f;
#pragma unroll
        for (int jj = 0; jj < KNB; jj++) {
            pj[jj] = __expf((pj[jj] - mx) * 0.08838834764831845f);
            sum += pj[jj];
        }
        float inv = 1.0f / sum;

        float4 acc0 = {0, 0, 0, 0}, acc1 = {0, 0, 0, 0};
#pragma unroll
        for (int jj = 0; jj < KNB; jj++) {
            float a = pj[jj] * inv;
            int nbj = __shfl_sync(0xffffffffu, nb, jj);
            const uint2* fv = (const uint2*)(g_featT + ((size_t)(b * NPTS) + nbj) * 256);
            uint2 u0 = fv[l];
            uint2 u1 = fv[32 + l];
            float2 f00 = __half22float2(*(const __half2*)&u0.x);
            float2 f01 = __half22float2(*(const __half2*)&u0.y);
            float2 f10 = __half22float2(*(const __half2*)&u1.x);
            float2 f11 = __half22float2(*(const __half2*)&u1.y);
            acc0.x = fmaf(a, f00.x, acc0.x); acc0.y = fmaf(a, f00.y, acc0.y);
            acc0.z = fmaf(a, f01.x, acc0.z); acc0.w = fmaf(a, f01.y, acc0.w);
            acc1.x = fmaf(a, f10.x, acc1.x); acc1.y = fmaf(a, f10.y, acc1.y);
            acc1.z = fmaf(a, f11.x, acc1.z); acc1.w = fmaf(a, f11.y, acc1.w);
        }

        int pr = w * 4 + i;
        int c0 = 4 * l;
        s_out[(c0 + 0) * 33 + pr] = acc0.x;
        s_out[(c0 + 1) * 33 + pr] = acc0.y;
        s_out[(c0 + 2) * 33 + pr] = acc0.z;
        s_out[(c0 + 3) * 33 + pr] = acc0.w;
        s_out[(128 + c0 + 0) * 33 + pr] = acc1.x;
        s_out[(128 + c0 + 1) * 33 + pr] = acc1.y;
        s_out[(128 + c0 + 2) * 33 + pr] = acc1.z;
        s_out[(128 + c0 + 3) * 33 + pr] = acc1.w;
    }
    __syncthreads();

    float* obase = out + (size_t)b * CCH * NPTS;
    int n0 = p0 & (NPTS - 1);
#pragma unroll
    for (int i = 0; i < 32; i++) {
        int linear = i * 256 + tid;
        int c  = linear >> 5;
        int nl = linear & 31;
        obase[(size_t)c * NPTS + n0 + nl] = s_out[c * 33 + nl];
    }
}

// ---------------------------------------------------------------------------
extern "C" void kernel_launch(void* const* d_in, const int* in_sizes, int n_in,
                              void* d_out, int out_size) {
    const float* xyz    = (const float*)d_in[0];
    const float* feat   = (const float*)d_in[1];
    const float* concat = (const float*)d_in[2];
    const float* Wq     = (const float*)d_in[3];
    const float* bq     = (const float*)d_in[4];
    const float* Wk     = (const float*)d_in[5];
    const float* bk     = (const float*)d_in[6];
    float* out = (float*)d_out;

    cudaFuncSetAttribute(knn_kernel, cudaFuncAttributeMaxDynamicSharedMemorySize, KNN_SMEM);
    cudaFuncSetAttribute(qk_gemm_kernel, cudaFuncAttributeMaxDynamicSharedMemorySize, GEMM_SMEM);

    dim3 tgrid(CCH / 32, NPTS / 32, BATCH);
    transpose_kernel<<<tgrid, dim3(32, 8)>>>(feat);
    knn_kernel<<<BATCH * 64, KNN_BLOCK, KNN_SMEM>>>(xyz);
    qk_gemm_kernel<<<(BATCH * NPTS / 64) * 2, 256, GEMM_SMEM>>>(concat, Wq, bq, Wk, bk);
    attn_kernel<<<(BATCH * NPTS) / 32, 256>>>(out);
}